// round 1
// baseline (speedup 1.0000x reference)
#include <cuda_runtime.h>
#include <math.h>

#define BB 32
#define TT 256
#define CC 128
#define TOPK 4
#define NEIGH 5

// ---------------- scratch (static device globals: no allocation) ----------------
__device__ float d_pf_buf[BB*TT*CC];   // 4 MB
__device__ float d_ns_buf[BB*TT*CC];   // 4 MB
__device__ float d_v_buf [BB*TT*CC];   // 4 MB
__device__ float d_G_buf [BB*TT*TT];   // 8 MB

// ---------------- K1: projections  out[t,c] = sum_k x[t,k] * W[c,k] ----------------
// grid = (B*T)/32 blocks, 128 threads; each thread = one output channel, 32 rows.
__global__ void proj_kernel(const float* __restrict__ x,
                            const float* __restrict__ W,
                            int which)
{
    __shared__ float xsh[32][CC];
    const int t0  = blockIdx.x * 32;
    const int tid = threadIdx.x;

    for (int i = tid; i < 32*CC; i += 128)
        xsh[i >> 7][i & 127] = x[t0*CC + i];
    __syncthreads();

    float acc[32];
    #pragma unroll
    for (int r = 0; r < 32; r++) acc[r] = 0.f;

    const float* wrow = W + tid * CC;
    for (int k0 = 0; k0 < CC; k0 += 16) {
        float w[16];
        const float4* wp = (const float4*)(wrow + k0);
        #pragma unroll
        for (int q = 0; q < 4; q++) {
            float4 t4 = wp[q];
            w[q*4+0]=t4.x; w[q*4+1]=t4.y; w[q*4+2]=t4.z; w[q*4+3]=t4.w;
        }
        #pragma unroll
        for (int r = 0; r < 32; r++) {
            const float4* xp = (const float4*)(&xsh[r][k0]);
            #pragma unroll
            for (int q = 0; q < 4; q++) {
                float4 xv = xp[q];
                acc[r] += xv.x*w[q*4+0] + xv.y*w[q*4+1] + xv.z*w[q*4+2] + xv.w*w[q*4+3];
            }
        }
    }
    float* outp = (which == 0) ? d_pf_buf : (which == 1) ? d_ns_buf : d_v_buf;
    #pragma unroll
    for (int r = 0; r < 32; r++)
        outp[(t0 + r)*CC + tid] = acc[r];
}

// ---------------- K2: row-normalize pf and ns ----------------
__global__ void norm_kernel()
{
    const int row = blockIdx.x;
    const int tid = threadIdx.x;
    float* buf = (blockIdx.y == 0) ? d_pf_buf : d_ns_buf;
    float v = buf[row*CC + tid];
    float s = v*v;
    #pragma unroll
    for (int o = 16; o > 0; o >>= 1) s += __shfl_xor_sync(0xffffffffu, s, o);
    __shared__ float ws[4];
    if ((tid & 31) == 0) ws[tid >> 5] = s;
    __syncthreads();
    float tot = ws[0] + ws[1] + ws[2] + ws[3];
    float d = fmaxf(sqrtf(tot), 1e-12f);
    buf[row*CC + tid] = v / d;
}

// ---------------- K3: per-batch Gram  G = pf @ pf^T ----------------
// grid = B*16 (64x64 tiles), 256 threads, 4x4 micro-tiles.
__global__ void gram_kernel()
{
    const int b    = blockIdx.x >> 4;
    const int tile = blockIdx.x & 15;
    const int x0 = (tile >> 2) << 6;
    const int y0 = (tile & 3)  << 6;
    const float* base = d_pf_buf + (size_t)b*TT*CC;

    __shared__ float As[16][68];
    __shared__ float Bs[16][68];

    const int tid = threadIdx.x;
    const int tx = tid & 15, ty = tid >> 4;
    const int lk = tid & 15, lr = tid >> 4;

    float acc[4][4];
    #pragma unroll
    for (int i = 0; i < 4; i++)
        #pragma unroll
        for (int j = 0; j < 4; j++) acc[i][j] = 0.f;

    for (int k0 = 0; k0 < CC; k0 += 16) {
        #pragma unroll
        for (int p = 0; p < 4; p++) {
            int r = lr + (p << 4);
            As[lk][r] = base[(x0 + r)*CC + k0 + lk];
            Bs[lk][r] = base[(y0 + r)*CC + k0 + lk];
        }
        __syncthreads();
        #pragma unroll
        for (int kk = 0; kk < 16; kk++) {
            float a[4], bb[4];
            #pragma unroll
            for (int i = 0; i < 4; i++) a[i]  = As[kk][ty*4 + i];
            #pragma unroll
            for (int j = 0; j < 4; j++) bb[j] = Bs[kk][tx*4 + j];
            #pragma unroll
            for (int i = 0; i < 4; i++)
                #pragma unroll
                for (int j = 0; j < 4; j++)
                    acc[i][j] += a[i] * bb[j];
        }
        __syncthreads();
    }
    float* Gp = d_G_buf + (size_t)b*TT*TT;
    #pragma unroll
    for (int i = 0; i < 4; i++) {
        float4 vv = make_float4(acc[i][0], acc[i][1], acc[i][2], acc[i][3]);
        *(float4*)&Gp[(x0 + ty*4 + i)*TT + y0 + tx*4] = vv;
    }
}

// ---------------- K4: fused attention (flash-style) ----------------
// grid = B*8 (x-tiles of 32), 256 threads.
// Thread owns row xA = tid>>3; computes 4 logits per y-tile (y group tid&7),
// and 16 output channels at c = 32*j + (tid&7)*4 + q (interleaved, bank-conflict free).
__global__ void attn_kernel(const int*  __restrict__ radj,
                            const int*  __restrict__ inxs,
                            const float* __restrict__ vpf,
                            const float* __restrict__ gpfv,
                            const float* __restrict__ vns,
                            const float* __restrict__ gnsv,
                            float* __restrict__ out)
{
    const int b  = blockIdx.x >> 3;
    const int x0 = (blockIdx.x & 7) << 5;
    const int tid = threadIdx.x;

    __shared__ float qsh[32][CC + 4];
    __shared__ float tile[32][CC + 4];   // ns then v, per y-tile
    __shared__ float Gsh[36][40];
    __shared__ float Ssh[32][33];
    __shared__ float wpf[NEIGH];
    __shared__ float wns[TOPK];

    if (tid == 0) {
        float n = 0.f;
        for (int i = 0; i < NEIGH; i++) n += vpf[i]*vpf[i];
        n = sqrtf(n);
        float g = gpfv[0];
        for (int i = 0; i < NEIGH; i++) wpf[i] = g * vpf[i] / n;
    }
    if (tid == 32) {
        float n = 0.f;
        for (int i = 0; i < TOPK; i++) n += vns[i]*vns[i];
        n = sqrtf(n);
        float g = gnsv[0];
        for (int i = 0; i < TOPK; i++) wns[i] = g * vns[i] / n;
    }
    __syncthreads();

    // gather q[x] = sum_n wns[n] * ns[inxs[x,n]]
    {
        const int c = tid & 127, xh = tid >> 7;
        for (int xx = 0; xx < 16; xx++) {
            const int x = (xx << 1) + xh;
            const int* ip = inxs + ((size_t)b*TT + x0 + x)*TOPK;
            float a = 0.f;
            #pragma unroll
            for (int n = 0; n < TOPK; n++)
                a += wns[n] * d_ns_buf[((size_t)b*TT + ip[n])*CC + c];
            qsh[x][c] = a;
        }
    }

    const int xA  = tid >> 3;
    const int yg8 = tid & 7;
    const int xg  = x0 + xA;
    const int startx = min(max(xg - 2, 0), TT - NEIGH);
    const int plo = max(x0 - 2, 0);
    const int phi = min(x0 + 33, TT - 1);
    const int pcnt = phi - plo + 1;

    float acc[16];
    #pragma unroll
    for (int j = 0; j < 16; j++) acc[j] = 0.f;
    float mrun = -3.0e38f, lrun = 0.f;

    for (int yt = 0; yt < 8; yt++) {
        const int y0 = yt << 5;
        __syncthreads();  // protect tile/Gsh/Ssh from previous iteration

        for (int i = tid; i < 32*CC; i += 256)
            tile[i >> 7][i & 127] = d_ns_buf[(((size_t)b*TT + y0) << 7) + i];

        const int ylo = max(y0 - 2, 0);
        const int yhi = min(y0 + 33, TT - 1);
        const int ycnt = yhi - ylo + 1;
        for (int i = tid; i < pcnt*ycnt; i += 256) {
            int pi = i / ycnt, yi = i - pi*ycnt;
            Gsh[pi][yi] = d_G_buf[(size_t)b*TT*TT + (plo + pi)*TT + ylo + yi];
        }
        __syncthreads();

        // ---- logits: sim_ns (dot) + sim_pf (windowed max of G) + mask ----
        float sv[4];
        {
            float s0 = 0.f, s1 = 0.f, s2 = 0.f, s3 = 0.f;
            const float4* q4 = (const float4*)qsh[xA];
            const float4* n0 = (const float4*)tile[(yg8 << 2) + 0];
            const float4* n1 = (const float4*)tile[(yg8 << 2) + 1];
            const float4* n2 = (const float4*)tile[(yg8 << 2) + 2];
            const float4* n3 = (const float4*)tile[(yg8 << 2) + 3];
            #pragma unroll 8
            for (int k = 0; k < 32; k++) {
                float4 qv = q4[k];
                float4 a = n0[k]; s0 += qv.x*a.x + qv.y*a.y + qv.z*a.z + qv.w*a.w;
                float4 c = n1[k]; s1 += qv.x*c.x + qv.y*c.y + qv.z*c.z + qv.w*c.w;
                float4 d = n2[k]; s2 += qv.x*d.x + qv.y*d.y + qv.z*d.z + qv.w*d.w;
                float4 e = n3[k]; s3 += qv.x*e.x + qv.y*e.y + qv.z*e.z + qv.w*e.w;
            }
            sv[0] = s0; sv[1] = s1; sv[2] = s2; sv[3] = s3;
        }
        #pragma unroll
        for (int e = 0; e < 4; e++) {
            const int y   = (yg8 << 2) + e;
            const int ygl = y0 + y;
            const int starty = min(max(ygl - 2, 0), TT - NEIGH);
            const int yoff = starty - ylo;
            float spf = 0.f;
            #pragma unroll
            for (int i = 0; i < NEIGH; i++) {
                const float* gr = Gsh[startx + i - plo];
                float mx = gr[yoff];
                #pragma unroll
                for (int j = 1; j < NEIGH; j++) mx = fmaxf(mx, gr[yoff + j]);
                spf += wpf[i] * mx;
            }
            float msk = (radj[((size_t)b*TT + xg)*TT + ygl] == 0) ? -1e22f : 0.f;
            sv[e] += spf + msk;
        }

        // ---- online softmax update (8 threads per row, xor-shuffle reduce) ----
        float lm = fmaxf(fmaxf(sv[0], sv[1]), fmaxf(sv[2], sv[3]));
        #pragma unroll
        for (int o = 1; o < 8; o <<= 1) lm = fmaxf(lm, __shfl_xor_sync(0xffffffffu, lm, o));
        float mnew = fmaxf(mrun, lm);
        float scale = __expf(mrun - mnew);
        float rs = 0.f;
        #pragma unroll
        for (int e = 0; e < 4; e++) {
            float p = __expf(sv[e] - mnew);
            Ssh[xA][(yg8 << 2) + e] = p;
            rs += p;
        }
        #pragma unroll
        for (int o = 1; o < 8; o <<= 1) rs += __shfl_xor_sync(0xffffffffu, rs, o);
        lrun = lrun * scale + rs;
        mrun = mnew;
        #pragma unroll
        for (int j = 0; j < 16; j++) acc[j] *= scale;
        __syncthreads();

        // ---- load v tile into the same buffer ----
        for (int i = tid; i < 32*CC; i += 256)
            tile[i >> 7][i & 127] = d_v_buf[(((size_t)b*TT + y0) << 7) + i];
        __syncthreads();

        // ---- PV accumulate ----
        #pragma unroll 4
        for (int y = 0; y < 32; y++) {
            float p = Ssh[xA][y];
            #pragma unroll
            for (int j = 0; j < 4; j++) {
                float4 vv = *(const float4*)&tile[y][(j << 5) + (yg8 << 2)];
                acc[j*4+0] += p * vv.x;
                acc[j*4+1] += p * vv.y;
                acc[j*4+2] += p * vv.z;
                acc[j*4+3] += p * vv.w;
            }
        }
    }

    const float inv = 1.f / lrun;
    const size_t row = ((size_t)b*TT + xg) * CC;
    #pragma unroll
    for (int j = 0; j < 4; j++) {
        float4 o4 = make_float4(acc[j*4+0]*inv, acc[j*4+1]*inv,
                                acc[j*4+2]*inv, acc[j*4+3]*inv);
        *(float4*)&out[row + (j << 5) + (yg8 << 2)] = o4;
    }
}

// ---------------- launch ----------------
extern "C" void kernel_launch(void* const* d_in, const int* in_sizes, int n_in,
                              void* d_out, int out_size)
{
    const float* x    = (const float*)d_in[0];
    const int*   radj = (const int*)  d_in[1];
    const int*   inxs = (const int*)  d_in[2];
    const float* Wpf  = (const float*)d_in[3];
    const float* Wns  = (const float*)d_in[4];
    const float* Wv   = (const float*)d_in[5];
    const float* vpf  = (const float*)d_in[6];
    const float* gpf  = (const float*)d_in[7];
    const float* vns  = (const float*)d_in[8];
    const float* gns  = (const float*)d_in[9];
    float* out = (float*)d_out;

    proj_kernel<<<(BB*TT)/32, 128>>>(x, Wpf, 0);
    proj_kernel<<<(BB*TT)/32, 128>>>(x, Wns, 1);
    proj_kernel<<<(BB*TT)/32, 128>>>(x, Wv,  2);
    norm_kernel<<<dim3(BB*TT, 2), 128>>>();
    gram_kernel<<<BB*16, 256>>>();
    attn_kernel<<<BB*8, 256>>>(radj, inxs, vpf, gpf, vns, gns, out);
}

// round 2
// speedup vs baseline: 1.1440x; 1.1440x over previous
#include <cuda_runtime.h>
#include <math.h>

#define BB 32
#define TT 256
#define CC 128
#define TOPK 4
#define NEIGH 5

// ---------------- scratch (static device globals: no allocation) ----------------
__device__ float d_pf_buf[BB*TT*CC];   // 4 MB (normalized pf)
__device__ float d_ns_buf[BB*TT*CC];   // 4 MB (normalized ns)
__device__ float d_v_buf [BB*TT*CC];   // 4 MB
__device__ float d_G_buf [BB*TT*TT];   // 8 MB

// ---------------- K1: fused projections + row-normalize ----------------
// grid = ((B*T)/32, 3), 128 threads. blockIdx.y selects W_pf / W_ns / W_v.
// Each thread owns one output channel for 32 rows. pf/ns are L2-normalized
// per row in-block (smem staging + warp reductions).
__global__ void proj_kernel(const float* __restrict__ x,
                            const float* __restrict__ Wpf,
                            const float* __restrict__ Wns,
                            const float* __restrict__ Wv)
{
    const int which = blockIdx.y;
    const float* __restrict__ W = (which == 0) ? Wpf : (which == 1) ? Wns : Wv;

    __shared__ float xsh[32][CC];
    __shared__ float osh[32][CC + 4];
    __shared__ float invn[32];

    const int t0  = blockIdx.x * 32;
    const int tid = threadIdx.x;

    for (int i = tid; i < 32*CC; i += 128)
        xsh[i >> 7][i & 127] = x[t0*CC + i];
    __syncthreads();

    float acc[32];
    #pragma unroll
    for (int r = 0; r < 32; r++) acc[r] = 0.f;

    const float* wrow = W + tid * CC;
    for (int k0 = 0; k0 < CC; k0 += 16) {
        float w[16];
        const float4* wp = (const float4*)(wrow + k0);
        #pragma unroll
        for (int q = 0; q < 4; q++) {
            float4 t4 = wp[q];
            w[q*4+0]=t4.x; w[q*4+1]=t4.y; w[q*4+2]=t4.z; w[q*4+3]=t4.w;
        }
        #pragma unroll
        for (int r = 0; r < 32; r++) {
            const float4* xp = (const float4*)(&xsh[r][k0]);
            #pragma unroll
            for (int q = 0; q < 4; q++) {
                float4 xv = xp[q];
                acc[r] += xv.x*w[q*4+0] + xv.y*w[q*4+1] + xv.z*w[q*4+2] + xv.w*w[q*4+3];
            }
        }
    }

    if (which == 2) {
        #pragma unroll
        for (int r = 0; r < 32; r++)
            d_v_buf[(t0 + r)*CC + tid] = acc[r];
        return;
    }

    #pragma unroll
    for (int r = 0; r < 32; r++) osh[r][tid] = acc[r];
    __syncthreads();

    {   // warp w normalizes rows [8w, 8w+8)
        const int w = tid >> 5, l = tid & 31;
        #pragma unroll
        for (int rr = 0; rr < 8; rr++) {
            const int r = (w << 3) + rr;
            float4 v4 = ((const float4*)osh[r])[l];
            float s = v4.x*v4.x + v4.y*v4.y + v4.z*v4.z + v4.w*v4.w;
            #pragma unroll
            for (int o = 16; o > 0; o >>= 1) s += __shfl_xor_sync(0xffffffffu, s, o);
            if (l == 0) invn[r] = 1.f / fmaxf(sqrtf(s), 1e-12f);
        }
    }
    __syncthreads();

    float* outp = (which == 0) ? d_pf_buf : d_ns_buf;
    #pragma unroll
    for (int r = 0; r < 32; r++)
        outp[(t0 + r)*CC + tid] = osh[r][tid] * invn[r];
}

// ---------------- K2: per-batch Gram  G = pf @ pf^T ----------------
__global__ void gram_kernel()
{
    const int b    = blockIdx.x >> 4;
    const int tile = blockIdx.x & 15;
    const int x0 = (tile >> 2) << 6;
    const int y0 = (tile & 3)  << 6;
    const float* base = d_pf_buf + (size_t)b*TT*CC;

    __shared__ float As[16][68];
    __shared__ float Bs[16][68];

    const int tid = threadIdx.x;
    const int tx = tid & 15, ty = tid >> 4;
    const int lk = tid & 15, lr = tid >> 4;

    float acc[4][4];
    #pragma unroll
    for (int i = 0; i < 4; i++)
        #pragma unroll
        for (int j = 0; j < 4; j++) acc[i][j] = 0.f;

    for (int k0 = 0; k0 < CC; k0 += 16) {
        #pragma unroll
        for (int p = 0; p < 4; p++) {
            int r = lr + (p << 4);
            As[lk][r] = base[(x0 + r)*CC + k0 + lk];
            Bs[lk][r] = base[(y0 + r)*CC + k0 + lk];
        }
        __syncthreads();
        #pragma unroll
        for (int kk = 0; kk < 16; kk++) {
            float a[4], bb[4];
            #pragma unroll
            for (int i = 0; i < 4; i++) a[i]  = As[kk][ty*4 + i];
            #pragma unroll
            for (int j = 0; j < 4; j++) bb[j] = Bs[kk][tx*4 + j];
            #pragma unroll
            for (int i = 0; i < 4; i++)
                #pragma unroll
                for (int j = 0; j < 4; j++)
                    acc[i][j] += a[i] * bb[j];
        }
        __syncthreads();
    }
    float* Gp = d_G_buf + (size_t)b*TT*TT;
    #pragma unroll
    for (int i = 0; i < 4; i++) {
        float4 vv = make_float4(acc[i][0], acc[i][1], acc[i][2], acc[i][3]);
        *(float4*)&Gp[(x0 + ty*4 + i)*TT + y0 + tx*4] = vv;
    }
}

// ---------------- K3: fused attention (flash-style) ----------------
// grid = B*8 (x-tiles of 32), 256 threads, 92KB dynamic smem.
// Full 36x256 G window loaded once per block. ns and v tiles loaded together.
struct AttnSmem {
    float qsh[32][CC + 4];
    float nsh[32][CC + 4];
    float vsh[32][CC + 4];
    float Gsh[36][260];
    float Ssh[32][33];
    float wpf[8];
    float wns[8];
};

__global__ void attn_kernel(const int*  __restrict__ radj,
                            const int*  __restrict__ inxs,
                            const float* __restrict__ vpf,
                            const float* __restrict__ gpfv,
                            const float* __restrict__ vns,
                            const float* __restrict__ gnsv,
                            float* __restrict__ out)
{
    extern __shared__ char smem_raw[];
    AttnSmem* S = (AttnSmem*)smem_raw;

    const int b  = blockIdx.x >> 3;
    const int x0 = (blockIdx.x & 7) << 5;
    const int tid = threadIdx.x;

    const int plo = max(x0 - 2, 0);
    const int phi = min(x0 + 33, TT - 1);
    const int pcnt = phi - plo + 1;

    if (tid == 0) {
        float n = 0.f;
        for (int i = 0; i < NEIGH; i++) n += vpf[i]*vpf[i];
        n = sqrtf(n);
        float g = gpfv[0];
        for (int i = 0; i < NEIGH; i++) S->wpf[i] = g * vpf[i] / n;
    }
    if (tid == 32) {
        float n = 0.f;
        for (int i = 0; i < TOPK; i++) n += vns[i]*vns[i];
        n = sqrtf(n);
        float g = gnsv[0];
        for (int i = 0; i < TOPK; i++) S->wns[i] = g * vns[i] / n;
    }
    __syncthreads();

    // ---- load full G window (coalesced float4) ----
    {
        const float* Gsrc = d_G_buf + (size_t)b*TT*TT;
        const int n4 = pcnt * 64;             // 64 float4 per 256-col row
        for (int i = tid; i < n4; i += 256) {
            int r = i >> 6, c = i & 63;
            ((float4*)S->Gsh[r])[c] = ((const float4*)(Gsrc + (size_t)(plo + r)*TT))[c];
        }
    }

    // ---- gather q[x] = sum_n wns[n] * ns[inxs[x,n]] ----
    {
        const int c = tid & 127, xh = tid >> 7;
        for (int xx = 0; xx < 16; xx++) {
            const int x = (xx << 1) + xh;
            const int* ip = inxs + ((size_t)b*TT + x0 + x)*TOPK;
            float a = 0.f;
            #pragma unroll
            for (int n = 0; n < TOPK; n++)
                a += S->wns[n] * d_ns_buf[((size_t)b*TT + ip[n])*CC + c];
            S->qsh[x][c] = a;
        }
    }

    const int xA  = tid >> 3;
    const int yg8 = tid & 7;
    const int xg  = x0 + xA;
    const int startx = min(max(xg - 2, 0), TT - NEIGH);

    float acc[16];
    #pragma unroll
    for (int j = 0; j < 16; j++) acc[j] = 0.f;
    float mrun = -3.0e38f, lrun = 0.f;

    float wpf_r[NEIGH];

    for (int yt = 0; yt < 8; yt++) {
        const int y0 = yt << 5;
        __syncthreads();  // protect nsh/vsh/Ssh from previous iter; qsh/Gsh on first

        // ---- load ns and v tiles together (2x MLP, one sync) ----
        {
            const size_t base = ((size_t)b*TT + y0) << 7;
            for (int i = tid; i < 32*(CC/4); i += 256) {
                int r = i >> 5, c4 = i & 31;
                ((float4*)S->nsh[r])[c4] = ((const float4*)(d_ns_buf + base + ((size_t)r << 7)))[c4];
                ((float4*)S->vsh[r])[c4] = ((const float4*)(d_v_buf  + base + ((size_t)r << 7)))[c4];
            }
        }
        if (yt == 0) {
            #pragma unroll
            for (int i = 0; i < NEIGH; i++) wpf_r[i] = S->wpf[i];
        }
        __syncthreads();

        // ---- logits: sim_ns (dot) + sim_pf (windowed max of G) + mask ----
        float sv[4];
        {
            float s0 = 0.f, s1 = 0.f, s2 = 0.f, s3 = 0.f;
            const float4* q4 = (const float4*)S->qsh[xA];
            const float4* n0 = (const float4*)S->nsh[(yg8 << 2) + 0];
            const float4* n1 = (const float4*)S->nsh[(yg8 << 2) + 1];
            const float4* n2 = (const float4*)S->nsh[(yg8 << 2) + 2];
            const float4* n3 = (const float4*)S->nsh[(yg8 << 2) + 3];
            #pragma unroll 8
            for (int k = 0; k < 32; k++) {
                float4 qv = q4[k];
                float4 a = n0[k]; s0 += qv.x*a.x + qv.y*a.y + qv.z*a.z + qv.w*a.w;
                float4 c = n1[k]; s1 += qv.x*c.x + qv.y*c.y + qv.z*c.z + qv.w*c.w;
                float4 d = n2[k]; s2 += qv.x*d.x + qv.y*d.y + qv.z*d.z + qv.w*d.w;
                float4 e = n3[k]; s3 += qv.x*e.x + qv.y*e.y + qv.z*e.z + qv.w*e.w;
            }
            sv[0] = s0; sv[1] = s1; sv[2] = s2; sv[3] = s3;
        }
        #pragma unroll
        for (int e = 0; e < 4; e++) {
            const int ygl = y0 + (yg8 << 2) + e;
            const int starty = min(max(ygl - 2, 0), TT - NEIGH);
            float spf = 0.f;
            #pragma unroll
            for (int i = 0; i < NEIGH; i++) {
                const float* gr = S->Gsh[startx + i - plo];
                float mx = gr[starty];
                #pragma unroll
                for (int j = 1; j < NEIGH; j++) mx = fmaxf(mx, gr[starty + j]);
                spf += wpf_r[i] * mx;
            }
            float msk = (radj[((size_t)b*TT + xg)*TT + ygl] == 0) ? -1e22f : 0.f;
            sv[e] += spf + msk;
        }

        // ---- online softmax update (8 threads per row) ----
        float lm = fmaxf(fmaxf(sv[0], sv[1]), fmaxf(sv[2], sv[3]));
        #pragma unroll
        for (int o = 1; o < 8; o <<= 1) lm = fmaxf(lm, __shfl_xor_sync(0xffffffffu, lm, o));
        float mnew = fmaxf(mrun, lm);
        float scale = __expf(mrun - mnew);
        float rs = 0.f;
        #pragma unroll
        for (int e = 0; e < 4; e++) {
            float p = __expf(sv[e] - mnew);
            S->Ssh[xA][(yg8 << 2) + e] = p;
            rs += p;
        }
        #pragma unroll
        for (int o = 1; o < 8; o <<= 1) rs += __shfl_xor_sync(0xffffffffu, rs, o);
        lrun = lrun * scale + rs;
        mrun = mnew;
        #pragma unroll
        for (int j = 0; j < 16; j++) acc[j] *= scale;
        __syncthreads();

        // ---- PV accumulate (v already resident) ----
        #pragma unroll 4
        for (int y = 0; y < 32; y++) {
            float p = S->Ssh[xA][y];
            #pragma unroll
            for (int j = 0; j < 4; j++) {
                float4 vv = *(const float4*)&S->vsh[y][(j << 5) + (yg8 << 2)];
                acc[j*4+0] += p * vv.x;
                acc[j*4+1] += p * vv.y;
                acc[j*4+2] += p * vv.z;
                acc[j*4+3] += p * vv.w;
            }
        }
    }

    const float inv = 1.f / lrun;
    const size_t row = ((size_t)b*TT + xg) * CC;
    #pragma unroll
    for (int j = 0; j < 4; j++) {
        float4 o4 = make_float4(acc[j*4+0]*inv, acc[j*4+1]*inv,
                                acc[j*4+2]*inv, acc[j*4+3]*inv);
        *(float4*)&out[row + (j << 5) + (yg8 << 2)] = o4;
    }
}

// ---------------- launch ----------------
extern "C" void kernel_launch(void* const* d_in, const int* in_sizes, int n_in,
                              void* d_out, int out_size)
{
    const float* x    = (const float*)d_in[0];
    const int*   radj = (const int*)  d_in[1];
    const int*   inxs = (const int*)  d_in[2];
    const float* Wpf  = (const float*)d_in[3];
    const float* Wns  = (const float*)d_in[4];
    const float* Wv   = (const float*)d_in[5];
    const float* vpf  = (const float*)d_in[6];
    const float* gpf  = (const float*)d_in[7];
    const float* vns  = (const float*)d_in[8];
    const float* gns  = (const float*)d_in[9];
    float* out = (float*)d_out;

    const int smem_bytes = (int)sizeof(AttnSmem);
    cudaFuncSetAttribute(attn_kernel, cudaFuncAttributeMaxDynamicSharedMemorySize, smem_bytes);

    proj_kernel<<<dim3((BB*TT)/32, 3), 128>>>(x, Wpf, Wns, Wv);
    gram_kernel<<<BB*16, 256>>>();
    attn_kernel<<<BB*8, 256, smem_bytes>>>(radj, inxs, vpf, gpf, vns, gns, out);
}

// round 5
// speedup vs baseline: 1.9175x; 1.6761x over previous
#include <cuda_runtime.h>
#include <math.h>

#define BB 32
#define TT 256
#define CC 128
#define TOPK 4
#define NEIGH 5

typedef unsigned long long u64;

__device__ __forceinline__ u64 pack2(float lo, float hi) {
    u64 r;
    asm("mov.b64 %0, {%1, %2};" : "=l"(r)
        : "r"(__float_as_uint(lo)), "r"(__float_as_uint(hi)));
    return r;
}
__device__ __forceinline__ void unpack2(u64 v, float& lo, float& hi) {
    unsigned a, b;
    asm("mov.b64 {%0, %1}, %2;" : "=r"(a), "=r"(b) : "l"(v));
    lo = __uint_as_float(a); hi = __uint_as_float(b);
}
__device__ __forceinline__ void ffma2(u64& d, u64 a, u64 b) {
    asm("fma.rn.f32x2 %0, %1, %2, %0;" : "+l"(d) : "l"(a), "l"(b));
}

// ---------------- scratch ----------------
__device__ float d_pf_buf[BB*TT*CC];
__device__ float d_ns_buf[BB*TT*CC];
__device__ float d_v_buf [BB*TT*CC];
__device__ float d_q_buf [BB*TT*CC];
__device__ float d_G_buf [BB*TT*TT];
__device__ float d_L_buf [BB*TT*TT];

// ---------------- K1: fused projections + row-normalize ----------------
// grid ((B*T)/32, 3), block 256. Thread = (channel c, row-half h); 16 rows each.
__global__ void proj_kernel(const float* __restrict__ x,
                            const float* __restrict__ Wpf,
                            const float* __restrict__ Wns,
                            const float* __restrict__ Wv)
{
    const int which = blockIdx.y;
    const float* __restrict__ W = (which == 0) ? Wpf : (which == 1) ? Wns : Wv;

    __shared__ float xsh[32][CC];
    __shared__ float osh[32][132];
    __shared__ float invn[32];

    const int t0  = blockIdx.x * 32;
    const int tid = threadIdx.x;
    const int c   = tid & 127;
    const int h   = tid >> 7;

    for (int i = tid; i < 32*32; i += 256) {
        int r = i >> 5, c4 = i & 31;
        *(float4*)&xsh[r][c4*4] = *(const float4*)&x[(t0 + r)*CC + c4*4];
    }
    __syncthreads();

    float acc[16];
    #pragma unroll
    for (int r = 0; r < 16; r++) acc[r] = 0.f;

    const float* wrow = W + c * CC;
    for (int k0 = 0; k0 < CC; k0 += 16) {
        float w[16];
        const float4* wp = (const float4*)(wrow + k0);
        #pragma unroll
        for (int q = 0; q < 4; q++) {
            float4 t4 = wp[q];
            w[q*4+0]=t4.x; w[q*4+1]=t4.y; w[q*4+2]=t4.z; w[q*4+3]=t4.w;
        }
        #pragma unroll
        for (int r = 0; r < 16; r++) {
            const int rr = h*16 + r;
            const float4* xp = (const float4*)(&xsh[rr][k0]);
            #pragma unroll
            for (int q = 0; q < 4; q++) {
                float4 xv = xp[q];
                acc[r] += xv.x*w[q*4+0] + xv.y*w[q*4+1] + xv.z*w[q*4+2] + xv.w*w[q*4+3];
            }
        }
    }

    if (which == 2) {
        #pragma unroll
        for (int r = 0; r < 16; r++)
            d_v_buf[(t0 + h*16 + r)*CC + c] = acc[r];
        return;
    }

    #pragma unroll
    for (int r = 0; r < 16; r++) osh[h*16 + r][c] = acc[r];
    __syncthreads();

    {   // 8 warps x 4 rows each
        const int wrp = tid >> 5, l = tid & 31;
        #pragma unroll
        for (int rr = 0; rr < 4; rr++) {
            const int r = wrp*4 + rr;
            float4 v4 = *(const float4*)&osh[r][l*4];
            float s = v4.x*v4.x + v4.y*v4.y + v4.z*v4.z + v4.w*v4.w;
            #pragma unroll
            for (int o = 16; o > 0; o >>= 1) s += __shfl_xor_sync(0xffffffffu, s, o);
            if (l == 0) invn[r] = 1.f / fmaxf(sqrtf(s), 1e-12f);
        }
    }
    __syncthreads();

    float* outp = (which == 0) ? d_pf_buf : d_ns_buf;
    #pragma unroll
    for (int r = 0; r < 16; r++) {
        const int rr = h*16 + r;
        outp[(t0 + rr)*CC + c] = osh[rr][c] * invn[rr];
    }
}

// ---------------- K2: q gather  q[g] = sum_n wns[n] * ns[b, inxs[g,n]] ----------------
// grid (B*T)/8 = 1024, block 256.
__global__ void qgather_kernel(const int* __restrict__ inxs,
                               const float* __restrict__ vns,
                               const float* __restrict__ gnsv)
{
    const int g0  = blockIdx.x * 8;
    const int tid = threadIdx.x;
    const int c   = tid & 127;
    const int rh  = tid >> 7;

    float w[TOPK];
    {
        float n = 0.f;
        #pragma unroll
        for (int i = 0; i < TOPK; i++) { float v = __ldg(&vns[i]); w[i] = v; n += v*v; }
        float sc = __ldg(&gnsv[0]) / sqrtf(n);
        #pragma unroll
        for (int i = 0; i < TOPK; i++) w[i] *= sc;
    }

    #pragma unroll
    for (int t = 0; t < 4; t++) {
        const int g = g0 + rh*4 + t;
        const int b = g >> 8;
        int4 id = ((const int4*)inxs)[g];
        float a = w[0]*d_ns_buf[((size_t)b*TT + id.x)*CC + c]
                + w[1]*d_ns_buf[((size_t)b*TT + id.y)*CC + c]
                + w[2]*d_ns_buf[((size_t)b*TT + id.z)*CC + c]
                + w[3]*d_ns_buf[((size_t)b*TT + id.w)*CC + c];
        d_q_buf[(size_t)g*CC + c] = a;
    }
}

// ---------------- K3: per-batch Gram  G = pf @ pf^T  (FFMA2, k-paired) ----------------
// grid B*16 (64x64 tiles), block 256, dynamic smem.
struct GramSmem { float A[64][132]; float Bv[64][132]; };

__global__ void gram_kernel()
{
    extern __shared__ char smr[];
    GramSmem* S = (GramSmem*)smr;

    const int b    = blockIdx.x >> 4;
    const int tile = blockIdx.x & 15;
    const int x0 = (tile >> 2) << 6;
    const int y0 = (tile & 3)  << 6;
    const float* base = d_pf_buf + (size_t)b*TT*CC;
    const int tid = threadIdx.x;

    for (int i = tid; i < 64*32; i += 256) {
        int r = i >> 5, c4 = i & 31;
        *(float4*)&S->A [r][c4*4] = *(const float4*)&base[(x0 + r)*CC + c4*4];
        *(float4*)&S->Bv[r][c4*4] = *(const float4*)&base[(y0 + r)*CC + c4*4];
    }
    __syncthreads();

    const int xg = tid >> 4;   // 16 groups, x = xg + 16p
    const int yg = tid & 15;   // 16 groups, y = yg + 16e

    u64 acc[4][4];
    #pragma unroll
    for (int p = 0; p < 4; p++)
        #pragma unroll
        for (int e = 0; e < 4; e++) acc[p][e] = 0ull;

    for (int kp = 0; kp < 64; kp++) {
        u64 a2[4], b2[4];
        #pragma unroll
        for (int p = 0; p < 4; p++) a2[p] = *(const u64*)&S->A [xg + 16*p][2*kp];
        #pragma unroll
        for (int e = 0; e < 4; e++) b2[e] = *(const u64*)&S->Bv[yg + 16*e][2*kp];
        #pragma unroll
        for (int p = 0; p < 4; p++)
            #pragma unroll
            for (int e = 0; e < 4; e++)
                ffma2(acc[p][e], a2[p], b2[e]);
    }

    float* Gp = d_G_buf + (size_t)b*TT*TT;
    #pragma unroll
    for (int p = 0; p < 4; p++)
        #pragma unroll
        for (int e = 0; e < 4; e++) {
            float lo, hi; unpack2(acc[p][e], lo, hi);
            Gp[(x0 + xg + 16*p)*TT + y0 + yg + 16*e] = lo + hi;
        }
}

// ---------------- K4: logits  L = q@ns^T + pf-window-max + mask ----------------
// grid B*8*4 = 1024 (32x rows x 64y cols per block), block 256, dynamic smem.
struct LKSmem { float q[32][132]; float ns[64][134]; float G[36][68]; float wpf[8]; };

__global__ void lk_kernel(const int* __restrict__ radj,
                          const float* __restrict__ vpf,
                          const float* __restrict__ gpfv)
{
    extern __shared__ char smr[];
    LKSmem* S = (LKSmem*)smr;

    const int b  = blockIdx.x >> 5;
    const int r5 = blockIdx.x & 31;
    const int x0 = (r5 >> 2) << 5;
    const int y0 = (r5 & 3)  << 6;
    const int tid = threadIdx.x;

    const int plo = max(x0 - 2, 0);
    const int ylo = max(y0 - 2, 0);

    if (tid == 0) {
        float n = 0.f;
        for (int i = 0; i < NEIGH; i++) n += vpf[i]*vpf[i];
        float sc = gpfv[0] / sqrtf(n);
        for (int i = 0; i < NEIGH; i++) S->wpf[i] = vpf[i] * sc;
    }

    for (int i = tid; i < 32*32; i += 256) {
        int r = i >> 5, c4 = i & 31;
        *(float4*)&S->q[r][c4*4] = *(const float4*)&d_q_buf[((size_t)b*TT + x0 + r)*CC + c4*4];
    }
    for (int i = tid; i < 64*32; i += 256) {
        int r = i >> 5, c4 = i & 31;
        float4 t4 = *(const float4*)&d_ns_buf[((size_t)b*TT + y0 + r)*CC + c4*4];
        *(float2*)&S->ns[r][c4*4 + 0] = make_float2(t4.x, t4.y);
        *(float2*)&S->ns[r][c4*4 + 2] = make_float2(t4.z, t4.w);
    }
    {
        const float* Gp = d_G_buf + (size_t)b*TT*TT;
        for (int i = tid; i < 36*68; i += 256) {
            int r = i / 68, cc2 = i - r*68;
            int row = min(plo + r, TT-1);
            int col = min(ylo + cc2, TT-1);
            S->G[r][cc2] = Gp[row*TT + col];
        }
    }
    __syncthreads();

    const int xg = tid >> 5;   // 8 groups, x = xg + 8p
    const int yg = tid & 31;   // 32 groups, y = yg + 32e

    u64 acc[4][2];
    #pragma unroll
    for (int p = 0; p < 4; p++) { acc[p][0] = 0ull; acc[p][1] = 0ull; }

    for (int kp = 0; kp < 64; kp++) {
        u64 q2[4], n2[2];
        #pragma unroll
        for (int p = 0; p < 4; p++) q2[p] = *(const u64*)&S->q [xg + 8*p ][2*kp];
        #pragma unroll
        for (int e = 0; e < 2; e++) n2[e] = *(const u64*)&S->ns[yg + 32*e][2*kp];
        #pragma unroll
        for (int p = 0; p < 4; p++) {
            ffma2(acc[p][0], q2[p], n2[0]);
            ffma2(acc[p][1], q2[p], n2[1]);
        }
    }

    float wpfr[NEIGH];
    #pragma unroll
    for (int i = 0; i < NEIGH; i++) wpfr[i] = S->wpf[i];

    float* Lp = d_L_buf + (size_t)b*TT*TT;
    #pragma unroll
    for (int p = 0; p < 4; p++) {
        const int xgl = x0 + xg + 8*p;
        const int startx = min(max(xgl - 2, 0), TT - NEIGH);
        const int sxr = startx - plo;
        #pragma unroll
        for (int e = 0; e < 2; e++) {
            const int ygl = y0 + yg + 32*e;
            const int starty = min(max(ygl - 2, 0), TT - NEIGH);
            const int syr = starty - ylo;
            float lo, hi; unpack2(acc[p][e], lo, hi);
            float s = lo + hi;
            float spf = 0.f;
            #pragma unroll
            for (int i = 0; i < NEIGH; i++) {
                const float* gr = S->G[sxr + i];
                float mx = gr[syr];
                #pragma unroll
                for (int j = 1; j < NEIGH; j++) mx = fmaxf(mx, gr[syr + j]);
                spf += wpfr[i] * mx;
            }
            float msk = (radj[((size_t)b*TT + xgl)*TT + ygl] == 0) ? -1e22f : 0.f;
            Lp[(size_t)xgl*TT + ygl] = s + spf + msk;
        }
    }
}

// ---------------- K5: out = softmax(L) @ v ----------------
// grid B*16 (16 x-rows per block), block 256.
__global__ void pv_kernel(float* __restrict__ out)
{
    __shared__ float Lsh[16][260];
    __shared__ float vsh[32][132];
    __shared__ float linv[16];

    const int b  = blockIdx.x >> 4;
    const int x0 = (blockIdx.x & 15) << 4;
    const int tid = threadIdx.x;

    const float* Lp = d_L_buf + (size_t)b*TT*TT;
    for (int i = tid; i < 16*64; i += 256) {
        int r = i >> 6, c4 = i & 63;
        *(float4*)&Lsh[r][c4*4] = *(const float4*)&Lp[(size_t)(x0 + r)*TT + c4*4];
    }
    __syncthreads();

    {   // softmax: warp w handles rows 2w, 2w+1
        const int wrp = tid >> 5, l = tid & 31;
        #pragma unroll
        for (int rr = 0; rr < 2; rr++) {
            const int r = wrp*2 + rr;
            float4 v0 = *(const float4*)&Lsh[r][l*8];
            float4 v1 = *(const float4*)&Lsh[r][l*8 + 4];
            float m = fmaxf(fmaxf(fmaxf(v0.x, v0.y), fmaxf(v0.z, v0.w)),
                            fmaxf(fmaxf(v1.x, v1.y), fmaxf(v1.z, v1.w)));
            #pragma unroll
            for (int o = 16; o > 0; o >>= 1) m = fmaxf(m, __shfl_xor_sync(0xffffffffu, m, o));
            v0.x = __expf(v0.x - m); v0.y = __expf(v0.y - m);
            v0.z = __expf(v0.z - m); v0.w = __expf(v0.w - m);
            v1.x = __expf(v1.x - m); v1.y = __expf(v1.y - m);
            v1.z = __expf(v1.z - m); v1.w = __expf(v1.w - m);
            float s = v0.x + v0.y + v0.z + v0.w + v1.x + v1.y + v1.z + v1.w;
            #pragma unroll
            for (int o = 16; o > 0; o >>= 1) s += __shfl_xor_sync(0xffffffffu, s, o);
            *(float4*)&Lsh[r][l*8]     = v0;
            *(float4*)&Lsh[r][l*8 + 4] = v1;
            if (l == 0) linv[r] = 1.f / s;
        }
    }
    __syncthreads();

    const int x  = tid >> 4;   // 16 rows
    const int cg = tid & 15;   // channels 2cg+32j+{0,1}

    u64 acc[4];
    #pragma unroll
    for (int j = 0; j < 4; j++) acc[j] = 0ull;

    for (int yt = 0; yt < 8; yt++) {
        for (int i = tid; i < 32*32; i += 256) {
            int r = i >> 5, c4 = i & 31;
            *(float4*)&vsh[r][c4*4] =
                *(const float4*)&d_v_buf[((size_t)b*TT + yt*32 + r)*CC + c4*4];
        }
        __syncthreads();

        #pragma unroll 4
        for (int y = 0; y < 32; y++) {
            float p = Lsh[x][yt*32 + y];
            u64 p2 = pack2(p, p);
            #pragma unroll
            for (int j = 0; j < 4; j++) {
                u64 v2 = *(const u64*)&vsh[y][2*cg + 32*j];
                ffma2(acc[j], p2, v2);
            }
        }
        __syncthreads();
    }

    const float inv = linv[x];
    const size_t row = ((size_t)b*TT + x0 + x) * CC;
    #pragma unroll
    for (int j = 0; j < 4; j++) {
        float lo, hi; unpack2(acc[j], lo, hi);
        *(float2*)&out[row + 2*cg + 32*j] = make_float2(lo*inv, hi*inv);
    }
}

// ---------------- launch ----------------
extern "C" void kernel_launch(void* const* d_in, const int* in_sizes, int n_in,
                              void* d_out, int out_size)
{
    const float* x    = (const float*)d_in[0];
    const int*   radj = (const int*)  d_in[1];
    const int*   inxs = (const int*)  d_in[2];
    const float* Wpf  = (const float*)d_in[3];
    const float* Wns  = (const float*)d_in[4];
    const float* Wv   = (const float*)d_in[5];
    const float* vpf  = (const float*)d_in[6];
    const float* gpf  = (const float*)d_in[7];
    const float* vns  = (const float*)d_in[8];
    const float* gns  = (const float*)d_in[9];
    float* out = (float*)d_out;

    const int gram_smem = (int)sizeof(GramSmem);
    const int lk_smem   = (int)sizeof(LKSmem);
    cudaFuncSetAttribute(gram_kernel, cudaFuncAttributeMaxDynamicSharedMemorySize, gram_smem);
    cudaFuncSetAttribute(lk_kernel,   cudaFuncAttributeMaxDynamicSharedMemorySize, lk_smem);

    proj_kernel<<<dim3((BB*TT)/32, 3), 256>>>(x, Wpf, Wns, Wv);
    qgather_kernel<<<(BB*TT)/8, 256>>>(inxs, vns, gns);
    gram_kernel<<<BB*16, 256, gram_smem>>>();
    lk_kernel<<<BB*32, 256, lk_smem>>>(radj, vpf, gpf);
    pv_kernel<<<BB*16, 256>>>(out);
}

// round 8
// speedup vs baseline: 2.2322x; 1.1641x over previous
#include <cuda_runtime.h>
#include <math.h>

#define BB 32
#define TT 256
#define CC 128
#define TOPK 4
#define NEIGH 5

typedef unsigned long long u64;

union F4U { float4 f4; u64 p[2]; float f[4]; };

__device__ __forceinline__ void ffma2(u64& d, u64 a, u64 b) {
    asm("fma.rn.f32x2 %0, %1, %2, %0;" : "+l"(d) : "l"(a), "l"(b));
}
__device__ __forceinline__ void fmul2(u64& d, u64 a) {
    asm("mul.rn.f32x2 %0, %0, %1;" : "+l"(d) : "l"(a));
}
__device__ __forceinline__ u64 pack2(float lo, float hi) {
    u64 r;
    asm("mov.b64 %0, {%1, %2};" : "=l"(r) : "r"(__float_as_uint(lo)), "r"(__float_as_uint(hi)));
    return r;
}
__device__ __forceinline__ void unpack2(u64 v, float& lo, float& hi) {
    unsigned a, b;
    asm("mov.b64 {%0, %1}, %2;" : "=r"(a), "=r"(b) : "l"(v));
    lo = __uint_as_float(a); hi = __uint_as_float(b);
}

// ---------------- scratch ----------------
__device__ float d_pf_buf[BB*TT*CC];
__device__ float d_ns_buf[BB*TT*CC];
__device__ float d_v_buf [BB*TT*CC];
__device__ float d_G_buf [BB*TT*TT];

// ---------------- K1: fused projections + row-normalize (FFMA2) ----------------
// grid ((B*T)/32, 3), block 256. Thread = (channel c, row-half h); 16 rows each.
// x operand is warp-broadcast from smem; W operand lives in registers.
__global__ __launch_bounds__(256) void proj_kernel(const float* __restrict__ x,
                            const float* __restrict__ Wpf,
                            const float* __restrict__ Wns,
                            const float* __restrict__ Wv)
{
    const int which = blockIdx.y;
    const float* __restrict__ W = (which == 0) ? Wpf : (which == 1) ? Wns : Wv;

    __shared__ float xsh[32][132];
    __shared__ float osh[32][132];
    __shared__ float invn[32];

    const int t0  = blockIdx.x * 32;
    const int tid = threadIdx.x;
    const int c   = tid & 127;
    const int h   = tid >> 7;

    for (int i = tid; i < 32*32; i += 256) {
        int r = i >> 5, c4 = i & 31;
        *(float4*)&xsh[r][c4*4] = *(const float4*)&x[(t0 + r)*CC + c4*4];
    }
    __syncthreads();

    u64 acc[16];
    #pragma unroll
    for (int r = 0; r < 16; r++) acc[r] = 0ull;

    const float* wrow = W + c * CC;
    for (int k0 = 0; k0 < CC; k0 += 16) {
        F4U w[4];
        const float4* wp = (const float4*)(wrow + k0);
        #pragma unroll
        for (int q = 0; q < 4; q++) w[q].f4 = wp[q];
        #pragma unroll
        for (int r = 0; r < 16; r++) {
            const int rr = h*16 + r;
            #pragma unroll
            for (int q = 0; q < 4; q++) {
                F4U xv; xv.f4 = *(const float4*)&xsh[rr][k0 + 4*q];
                ffma2(acc[r], xv.p[0], w[q].p[0]);
                ffma2(acc[r], xv.p[1], w[q].p[1]);
            }
        }
    }

    float accf[16];
    #pragma unroll
    for (int r = 0; r < 16; r++) {
        float lo, hi; unpack2(acc[r], lo, hi);
        accf[r] = lo + hi;
    }

    if (which == 2) {
        #pragma unroll
        for (int r = 0; r < 16; r++)
            d_v_buf[(t0 + h*16 + r)*CC + c] = accf[r];
        return;
    }

    #pragma unroll
    for (int r = 0; r < 16; r++) osh[h*16 + r][c] = accf[r];
    __syncthreads();

    {   // 8 warps x 4 rows each
        const int wrp = tid >> 5, l = tid & 31;
        #pragma unroll
        for (int rr = 0; rr < 4; rr++) {
            const int r = wrp*4 + rr;
            float4 v4 = *(const float4*)&osh[r][l*4];
            float s = v4.x*v4.x + v4.y*v4.y + v4.z*v4.z + v4.w*v4.w;
            #pragma unroll
            for (int o = 16; o > 0; o >>= 1) s += __shfl_xor_sync(0xffffffffu, s, o);
            if (l == 0) invn[r] = 1.f / fmaxf(sqrtf(s), 1e-12f);
        }
    }
    __syncthreads();

    float* outp = (which == 0) ? d_pf_buf : d_ns_buf;
    #pragma unroll
    for (int r = 0; r < 16; r++) {
        const int rr = h*16 + r;
        outp[(t0 + rr)*CC + c] = osh[rr][c] * invn[rr];
    }
}

// ---------------- K2: per-batch Gram  G = pf @ pf^T  (FFMA2, LDS.128) ----------------
struct GramSmem { float A[64][132]; float Bv[64][132]; };

__global__ __launch_bounds__(256) void gram_kernel()
{
    extern __shared__ char smr[];
    GramSmem* S = (GramSmem*)smr;

    const int b    = blockIdx.x >> 4;
    const int tile = blockIdx.x & 15;
    const int x0 = (tile >> 2) << 6;
    const int y0 = (tile & 3)  << 6;
    const float* base = d_pf_buf + (size_t)b*TT*CC;
    const int tid = threadIdx.x;

    for (int i = tid; i < 64*32; i += 256) {
        int r = i >> 5, c4 = i & 31;
        *(float4*)&S->A [r][c4*4] = *(const float4*)&base[(x0 + r)*CC + c4*4];
        *(float4*)&S->Bv[r][c4*4] = *(const float4*)&base[(y0 + r)*CC + c4*4];
    }
    __syncthreads();

    const int xg = tid >> 4;   // 16 groups, x = xg + 16p
    const int yg = tid & 15;   // 16 groups, y = yg + 16e

    u64 acc[4][4];
    #pragma unroll
    for (int p = 0; p < 4; p++)
        #pragma unroll
        for (int e = 0; e < 4; e++) acc[p][e] = 0ull;

    for (int k4 = 0; k4 < 32; k4++) {          // 4 k per iter
        F4U a[4], bb[4];
        #pragma unroll
        for (int p = 0; p < 4; p++) a[p].f4  = *(const float4*)&S->A [xg + 16*p][4*k4];
        #pragma unroll
        for (int e = 0; e < 4; e++) bb[e].f4 = *(const float4*)&S->Bv[yg + 16*e][4*k4];
        #pragma unroll
        for (int p = 0; p < 4; p++)
            #pragma unroll
            for (int e = 0; e < 4; e++) {
                ffma2(acc[p][e], a[p].p[0], bb[e].p[0]);
                ffma2(acc[p][e], a[p].p[1], bb[e].p[1]);
            }
    }

    float* Gp = d_G_buf + (size_t)b*TT*TT;
    #pragma unroll
    for (int p = 0; p < 4; p++)
        #pragma unroll
        for (int e = 0; e < 4; e++) {
            float lo, hi; unpack2(acc[p][e], lo, hi);
            Gp[(x0 + xg + 16*p)*TT + y0 + yg + 16*e] = lo + hi;
        }
}

// ---------------- K3: fused flash attention (qgather + logits + softmax + PV) ----------------
// grid B*8 = 256 blocks (32 x-rows each), block 256, ~111KB dynamic smem.
struct AttnSmem {
    float q [32][132];
    float ns[64][132];
    float v [64][132];
    float G [36][68];
    int   rs[32][64];
    float P [64][33];
    float scl[32];
    float lsh[32];
    float wpf[8];
    float wns[8];
};

__global__ __launch_bounds__(256) void attn_kernel(const int*  __restrict__ radj,
                            const int*  __restrict__ inxs,
                            const float* __restrict__ vpf,
                            const float* __restrict__ gpfv,
                            const float* __restrict__ vns,
                            const float* __restrict__ gnsv,
                            float* __restrict__ out)
{
    extern __shared__ char smr[];
    AttnSmem* S = (AttnSmem*)smr;

    const int b  = blockIdx.x >> 3;
    const int x0 = (blockIdx.x & 7) << 5;
    const int tid = threadIdx.x;
    const int plo = max(x0 - 2, 0);

    if (tid == 0) {
        float n = 0.f;
        for (int i = 0; i < NEIGH; i++) n += vpf[i]*vpf[i];
        float sc = gpfv[0] / sqrtf(n);
        for (int i = 0; i < NEIGH; i++) S->wpf[i] = vpf[i] * sc;
    }
    if (tid == 32) {
        float n = 0.f;
        for (int i = 0; i < TOPK; i++) n += vns[i]*vns[i];
        float sc = gnsv[0] / sqrtf(n);
        for (int i = 0; i < TOPK; i++) S->wns[i] = vns[i] * sc;
    }
    __syncthreads();

    // ---- q gather: row r = tid>>3, 16 channels per thread ----
    {
        const int r  = tid >> 3;
        const int cb = (tid & 7) * 16;
        int4 id = ((const int4*)inxs)[b*TT + x0 + r];
        float w0 = S->wns[0], w1 = S->wns[1], w2 = S->wns[2], w3 = S->wns[3];
        const float* nsb = d_ns_buf + (size_t)b*TT*CC;
        #pragma unroll
        for (int j = 0; j < 4; j++) {
            const int c = cb + 4*j;
            float4 a0 = *(const float4*)&nsb[(size_t)id.x*CC + c];
            float4 a1 = *(const float4*)&nsb[(size_t)id.y*CC + c];
            float4 a2 = *(const float4*)&nsb[(size_t)id.z*CC + c];
            float4 a3 = *(const float4*)&nsb[(size_t)id.w*CC + c];
            float4 o;
            o.x = w0*a0.x + w1*a1.x + w2*a2.x + w3*a3.x;
            o.y = w0*a0.y + w1*a1.y + w2*a2.y + w3*a3.y;
            o.z = w0*a0.z + w1*a1.z + w2*a2.z + w3*a3.z;
            o.w = w0*a0.w + w1*a1.w + w2*a2.w + w3*a3.w;
            *(float4*)&S->q[r][c] = o;
        }
    }

    const int xg  = tid >> 5;                 // logits rows: xg + 8p (warp-local rows)
    const int ygl = tid & 31;                 // logits cols: ygl + 32e
    const int xq  = tid >> 4;                 // PV rows: xq, xq+16
    const int cgq = tid & 15;                 // PV channels: 4cgq..+3 and 64+4cgq..+3

    float mrun[4], lrun[4];
    #pragma unroll
    for (int p = 0; p < 4; p++) { mrun[p] = -3.0e38f; lrun[p] = 0.f; }

    u64 oacc[2][4];                            // 2 rows x 8 ch (4 u64)
    #pragma unroll
    for (int r = 0; r < 2; r++)
        #pragma unroll
        for (int j = 0; j < 4; j++) oacc[r][j] = 0ull;

    for (int yt = 0; yt < 4; yt++) {
        const int y0 = yt << 6;
        const int ylo = max(y0 - 2, 0);
        __syncthreads();   // protect smem from previous iteration's readers

        // ---- stage ns, v (64x128 each), G window (36x68), radj (32x64) ----
        {
            const size_t base = ((size_t)b*TT + y0) << 7;
            for (int i = tid; i < 64*32; i += 256) {
                int r = i >> 5, c4 = i & 31;
                *(float4*)&S->ns[r][c4*4] = *(const float4*)(d_ns_buf + base + ((size_t)r << 7) + c4*4);
                *(float4*)&S->v [r][c4*4] = *(const float4*)(d_v_buf  + base + ((size_t)r << 7) + c4*4);
            }
            const float* Gp = d_G_buf + (size_t)b*TT*TT;
            for (int i = tid; i < 36*68; i += 256) {
                int r = i / 68, cc2 = i - r*68;
                int row = min(plo + r, TT-1);
                int col = min(ylo + cc2, TT-1);
                S->G[r][cc2] = Gp[row*TT + col];
            }
            for (int i = tid; i < 32*16; i += 256) {   // 512 int4
                int r = i >> 4, c4 = i & 15;
                ((int4*)S->rs[r])[c4] = *(const int4*)&radj[((size_t)b*TT + x0 + r)*TT + y0 + c4*4];
            }
        }
        __syncthreads();

        // ---- logits GEMM: 4 rows x 2 cols per thread ----
        u64 lacc[4][2];
        #pragma unroll
        for (int p = 0; p < 4; p++) { lacc[p][0] = 0ull; lacc[p][1] = 0ull; }

        for (int k4 = 0; k4 < 32; k4++) {
            F4U a[4], bb[2];
            #pragma unroll
            for (int p = 0; p < 4; p++) a[p].f4  = *(const float4*)&S->q [xg + 8*p ][4*k4];
            #pragma unroll
            for (int e = 0; e < 2; e++) bb[e].f4 = *(const float4*)&S->ns[ygl + 32*e][4*k4];
            #pragma unroll
            for (int p = 0; p < 4; p++)
                #pragma unroll
                for (int e = 0; e < 2; e++) {
                    ffma2(lacc[p][e], a[p].p[0], bb[e].p[0]);
                    ffma2(lacc[p][e], a[p].p[1], bb[e].p[1]);
                }
        }

        // ---- epilogue: + window-max + mask ----
        float wpfr[NEIGH];
        #pragma unroll
        for (int i = 0; i < NEIGH; i++) wpfr[i] = S->wpf[i];

        float sv[4][2];
        #pragma unroll
        for (int p = 0; p < 4; p++) {
            const int xl  = xg + 8*p;
            const int xgl = x0 + xl;
            const int startx = min(max(xgl - 2, 0), TT - NEIGH);
            const int sxr = startx - plo;
            #pragma unroll
            for (int e = 0; e < 2; e++) {
                const int yl  = ygl + 32*e;
                const int ygg = y0 + yl;
                const int starty = min(max(ygg - 2, 0), TT - NEIGH);
                const int syr = starty - ylo;
                float lo, hi; unpack2(lacc[p][e], lo, hi);
                float s = lo + hi;
                float spf = 0.f;
                #pragma unroll
                for (int i = 0; i < NEIGH; i++) {
                    const float* gr = S->G[sxr + i];
                    float mx = gr[syr];
                    #pragma unroll
                    for (int j = 1; j < NEIGH; j++) mx = fmaxf(mx, gr[syr + j]);
                    spf += wpfr[i] * mx;
                }
                float msk = (S->rs[xl][yl] == 0) ? -1e22f : 0.f;
                sv[p][e] = s + spf + msk;
            }
        }

        // ---- online softmax per row (row fully inside this warp) ----
        #pragma unroll
        for (int p = 0; p < 4; p++) {
            const int xl = xg + 8*p;
            float lm = fmaxf(sv[p][0], sv[p][1]);
            #pragma unroll
            for (int o = 16; o > 0; o >>= 1) lm = fmaxf(lm, __shfl_xor_sync(0xffffffffu, lm, o));
            float mnew = fmaxf(mrun[p], lm);
            float scale = __expf(mrun[p] - mnew);
            float p0 = __expf(sv[p][0] - mnew);
            float p1 = __expf(sv[p][1] - mnew);
            S->P[ygl     ][xl] = p0;
            S->P[ygl + 32][xl] = p1;
            float rs = p0 + p1;
            #pragma unroll
            for (int o = 16; o > 0; o >>= 1) rs += __shfl_xor_sync(0xffffffffu, rs, o);
            lrun[p] = lrun[p] * scale + rs;
            mrun[p] = mnew;
            if ((tid & 31) == 0) S->scl[xl] = scale;
        }
        __syncthreads();

        // ---- PV: rescale accs then accumulate this tile ----
        {
            u64 s0 = pack2(S->scl[xq], S->scl[xq]);
            u64 s1 = pack2(S->scl[xq + 16], S->scl[xq + 16]);
            #pragma unroll
            for (int j = 0; j < 4; j++) { fmul2(oacc[0][j], s0); fmul2(oacc[1][j], s1); }
        }
        #pragma unroll 4
        for (int y = 0; y < 64; y++) {
            float pa = S->P[y][xq];
            float pb = S->P[y][xq + 16];
            u64 pa2 = pack2(pa, pa);
            u64 pb2 = pack2(pb, pb);
            F4U v0, v1;
            v0.f4 = *(const float4*)&S->v[y][4*cgq];
            v1.f4 = *(const float4*)&S->v[y][64 + 4*cgq];
            ffma2(oacc[0][0], pa2, v0.p[0]);
            ffma2(oacc[0][1], pa2, v0.p[1]);
            ffma2(oacc[0][2], pa2, v1.p[0]);
            ffma2(oacc[0][3], pa2, v1.p[1]);
            ffma2(oacc[1][0], pb2, v0.p[0]);
            ffma2(oacc[1][1], pb2, v0.p[1]);
            ffma2(oacc[1][2], pb2, v1.p[0]);
            ffma2(oacc[1][3], pb2, v1.p[1]);
        }
    }

    // ---- finalize ----
    if ((tid & 31) == 0) {
        #pragma unroll
        for (int p = 0; p < 4; p++) S->lsh[xg + 8*p] = lrun[p];
    }
    __syncthreads();

    #pragma unroll
    for (int r = 0; r < 2; r++) {
        const int xl = xq + 16*r;
        const float inv = 1.f / S->lsh[xl];
        const size_t row = ((size_t)b*TT + x0 + xl) * CC;
        F4U o0, o1;
        unpack2(oacc[r][0], o0.f[0], o0.f[1]);
        unpack2(oacc[r][1], o0.f[2], o0.f[3]);
        unpack2(oacc[r][2], o1.f[0], o1.f[1]);
        unpack2(oacc[r][3], o1.f[2], o1.f[3]);
        #pragma unroll
        for (int j = 0; j < 4; j++) { o0.f[j] *= inv; o1.f[j] *= inv; }
        *(float4*)&out[row + 4*cgq]      = o0.f4;
        *(float4*)&out[row + 64 + 4*cgq] = o1.f4;
    }
}

// ---------------- launch ----------------
extern "C" void kernel_launch(void* const* d_in, const int* in_sizes, int n_in,
                              void* d_out, int out_size)
{
    const float* x    = (const float*)d_in[0];
    const int*   radj = (const int*)  d_in[1];
    const int*   inxs = (const int*)  d_in[2];
    const float* Wpf  = (const float*)d_in[3];
    const float* Wns  = (const float*)d_in[4];
    const float* Wv   = (const float*)d_in[5];
    const float* vpf  = (const float*)d_in[6];
    const float* gpf  = (const float*)d_in[7];
    const float* vns  = (const float*)d_in[8];
    const float* gns  = (const float*)d_in[9];
    float* out = (float*)d_out;

    const int gram_smem = (int)sizeof(GramSmem);
    const int attn_smem = (int)sizeof(AttnSmem);
    cudaFuncSetAttribute(gram_kernel, cudaFuncAttributeMaxDynamicSharedMemorySize, gram_smem);
    cudaFuncSetAttribute(attn_kernel, cudaFuncAttributeMaxDynamicSharedMemorySize, attn_smem);

    proj_kernel<<<dim3((BB*TT)/32, 3), 256>>>(x, Wpf, Wns, Wv);
    gram_kernel<<<BB*16, 256, gram_smem>>>();
    attn_kernel<<<BB*8, 256, attn_smem>>>(radj, inxs, vpf, gpf, vns, gns, out);
}

// round 10
// speedup vs baseline: 2.7119x; 1.2149x over previous
#include <cuda_runtime.h>
#include <math.h>

#define BB 32
#define TT 256
#define CC 128
#define TOPK 4
#define NEIGH 5

typedef unsigned long long u64;

union F4U { float4 f4; u64 p[2]; float f[4]; };

__device__ __forceinline__ void ffma2(u64& d, u64 a, u64 b) {
    asm("fma.rn.f32x2 %0, %1, %2, %0;" : "+l"(d) : "l"(a), "l"(b));
}
__device__ __forceinline__ void fmul2(u64& d, u64 a) {
    asm("mul.rn.f32x2 %0, %0, %1;" : "+l"(d) : "l"(a));
}
__device__ __forceinline__ u64 pack2(float lo, float hi) {
    u64 r;
    asm("mov.b64 %0, {%1, %2};" : "=l"(r) : "r"(__float_as_uint(lo)), "r"(__float_as_uint(hi)));
    return r;
}
__device__ __forceinline__ void unpack2(u64 v, float& lo, float& hi) {
    unsigned a, b;
    asm("mov.b64 {%0, %1}, %2;" : "=r"(a), "=r"(b) : "l"(v));
    lo = __uint_as_float(a); hi = __uint_as_float(b);
}

// ---------------- scratch ----------------
__device__ float d_pf_buf[BB*TT*CC];
__device__ float d_ns_buf[BB*TT*CC];
__device__ float d_v_buf [BB*TT*CC];
__device__ float d_G_buf [BB*TT*TT];

// ---------------- K1: projections + row-normalize (smem-staged GEMM) ----------------
// grid ((B*T)/32, 3), block 256. Warp w owns rows 4w..4w+3; lane l owns cols l+32j.
// W staged through smem in coalesced 128x32 chunks (kills the 32-line LDG pattern).
__global__ __launch_bounds__(256) void proj_kernel(const float* __restrict__ x,
                            const float* __restrict__ Wpf,
                            const float* __restrict__ Wns,
                            const float* __restrict__ Wv)
{
    const int which = blockIdx.y;
    const float* __restrict__ W = (which == 0) ? Wpf : (which == 1) ? Wns : Wv;

    __shared__ float xsh[32][132];
    __shared__ float Wsh[128][36];

    const int t0  = blockIdx.x * 32;
    const int tid = threadIdx.x;
    const int rw  = tid >> 5;     // warp id -> rows rw*4..rw*4+3
    const int l   = tid & 31;     // lane   -> cols l + 32j

    for (int i = tid; i < 32*32; i += 256) {
        int r = i >> 5, c4 = i & 31;
        *(float4*)&xsh[r][c4*4] = *(const float4*)&x[(t0 + r)*CC + c4*4];
    }

    u64 acc[4][4];
    #pragma unroll
    for (int i = 0; i < 4; i++)
        #pragma unroll
        for (int j = 0; j < 4; j++) acc[i][j] = 0ull;

    for (int k0 = 0; k0 < CC; k0 += 32) {
        __syncthreads();
        // stage W chunk [128 rows][32 k] coalesced: 1024 float4, 4 per thread
        for (int i = tid; i < 128*8; i += 256) {
            int r = i >> 3, k4 = i & 7;
            *(float4*)&Wsh[r][k4*4] = *(const float4*)&W[r*CC + k0 + k4*4];
        }
        __syncthreads();

        #pragma unroll
        for (int k4 = 0; k4 < 8; k4++) {
            F4U a[4], bb[4];
            #pragma unroll
            for (int i = 0; i < 4; i++) a[i].f4  = *(const float4*)&xsh[rw*4 + i][k0 + 4*k4];
            #pragma unroll
            for (int j = 0; j < 4; j++) bb[j].f4 = *(const float4*)&Wsh[l + 32*j][4*k4];
            #pragma unroll
            for (int i = 0; i < 4; i++)
                #pragma unroll
                for (int j = 0; j < 4; j++) {
                    ffma2(acc[i][j], a[i].p[0], bb[j].p[0]);
                    ffma2(acc[i][j], a[i].p[1], bb[j].p[1]);
                }
        }
    }

    float o[4][4];
    #pragma unroll
    for (int i = 0; i < 4; i++)
        #pragma unroll
        for (int j = 0; j < 4; j++) {
            float lo, hi; unpack2(acc[i][j], lo, hi);
            o[i][j] = lo + hi;
        }

    float* outp = (which == 0) ? d_pf_buf : (which == 1) ? d_ns_buf : d_v_buf;

    if (which != 2) {
        // per-row L2 norm: each row lives entirely in this warp (4 cols/lane)
        #pragma unroll
        for (int i = 0; i < 4; i++) {
            float s = o[i][0]*o[i][0] + o[i][1]*o[i][1] + o[i][2]*o[i][2] + o[i][3]*o[i][3];
            #pragma unroll
            for (int off = 16; off > 0; off >>= 1) s += __shfl_xor_sync(0xffffffffu, s, off);
            float inv = 1.f / fmaxf(sqrtf(s), 1e-12f);
            #pragma unroll
            for (int j = 0; j < 4; j++) o[i][j] *= inv;
        }
    }

    #pragma unroll
    for (int i = 0; i < 4; i++) {
        const size_t row = (size_t)(t0 + rw*4 + i) * CC;
        #pragma unroll
        for (int j = 0; j < 4; j++)
            outp[row + l + 32*j] = o[i][j];
    }
}

// ---------------- K2: per-batch Gram  G = pf @ pf^T  (FFMA2, LDS.128) ----------------
struct GramSmem { float A[64][132]; float Bv[64][132]; };

__global__ __launch_bounds__(256) void gram_kernel()
{
    extern __shared__ char smr[];
    GramSmem* S = (GramSmem*)smr;

    const int b    = blockIdx.x >> 4;
    const int tile = blockIdx.x & 15;
    const int x0 = (tile >> 2) << 6;
    const int y0 = (tile & 3)  << 6;
    const float* base = d_pf_buf + (size_t)b*TT*CC;
    const int tid = threadIdx.x;

    for (int i = tid; i < 64*32; i += 256) {
        int r = i >> 5, c4 = i & 31;
        *(float4*)&S->A [r][c4*4] = *(const float4*)&base[(x0 + r)*CC + c4*4];
        *(float4*)&S->Bv[r][c4*4] = *(const float4*)&base[(y0 + r)*CC + c4*4];
    }
    __syncthreads();

    const int xg = tid >> 4;   // 16 groups, x = xg + 16p
    const int yg = tid & 15;   // 16 groups, y = yg + 16e

    u64 acc[4][4];
    #pragma unroll
    for (int p = 0; p < 4; p++)
        #pragma unroll
        for (int e = 0; e < 4; e++) acc[p][e] = 0ull;

    for (int k4 = 0; k4 < 32; k4++) {          // 4 k per iter
        F4U a[4], bb[4];
        #pragma unroll
        for (int p = 0; p < 4; p++) a[p].f4  = *(const float4*)&S->A [xg + 16*p][4*k4];
        #pragma unroll
        for (int e = 0; e < 4; e++) bb[e].f4 = *(const float4*)&S->Bv[yg + 16*e][4*k4];
        #pragma unroll
        for (int p = 0; p < 4; p++)
            #pragma unroll
            for (int e = 0; e < 4; e++) {
                ffma2(acc[p][e], a[p].p[0], bb[e].p[0]);
                ffma2(acc[p][e], a[p].p[1], bb[e].p[1]);
            }
    }

    float* Gp = d_G_buf + (size_t)b*TT*TT;
    #pragma unroll
    for (int p = 0; p < 4; p++)
        #pragma unroll
        for (int e = 0; e < 4; e++) {
            float lo, hi; unpack2(acc[p][e], lo, hi);
            Gp[(x0 + xg + 16*p)*TT + y0 + yg + 16*e] = lo + hi;
        }
}

// ---------------- K3: fused flash attention (qgather + logits + softmax + PV) ----------------
// grid B*8 = 256 blocks (32 x-rows each), block 256, ~111KB dynamic smem.
struct AttnSmem {
    float q [32][132];
    float ns[64][132];
    float v [64][132];
    float G [36][68];
    int   rs[32][64];
    float P [64][33];
    float scl[32];
    float lsh[32];
    float wpf[8];
    float wns[8];
};

__global__ __launch_bounds__(256) void attn_kernel(const int*  __restrict__ radj,
                            const int*  __restrict__ inxs,
                            const float* __restrict__ vpf,
                            const float* __restrict__ gpfv,
                            const float* __restrict__ vns,
                            const float* __restrict__ gnsv,
                            float* __restrict__ out)
{
    extern __shared__ char smr[];
    AttnSmem* S = (AttnSmem*)smr;

    const int b  = blockIdx.x >> 3;
    const int x0 = (blockIdx.x & 7) << 5;
    const int tid = threadIdx.x;
    const int plo = max(x0 - 2, 0);

    if (tid == 0) {
        float n = 0.f;
        for (int i = 0; i < NEIGH; i++) n += vpf[i]*vpf[i];
        float sc = gpfv[0] / sqrtf(n);
        for (int i = 0; i < NEIGH; i++) S->wpf[i] = vpf[i] * sc;
    }
    if (tid == 32) {
        float n = 0.f;
        for (int i = 0; i < TOPK; i++) n += vns[i]*vns[i];
        float sc = gnsv[0] / sqrtf(n);
        for (int i = 0; i < TOPK; i++) S->wns[i] = vns[i] * sc;
    }
    __syncthreads();

    // ---- q gather: row r = tid>>3, 16 channels per thread ----
    {
        const int r  = tid >> 3;
        const int cb = (tid & 7) * 16;
        int4 id = ((const int4*)inxs)[b*TT + x0 + r];
        float w0 = S->wns[0], w1 = S->wns[1], w2 = S->wns[2], w3 = S->wns[3];
        const float* nsb = d_ns_buf + (size_t)b*TT*CC;
        #pragma unroll
        for (int j = 0; j < 4; j++) {
            const int c = cb + 4*j;
            float4 a0 = *(const float4*)&nsb[(size_t)id.x*CC + c];
            float4 a1 = *(const float4*)&nsb[(size_t)id.y*CC + c];
            float4 a2 = *(const float4*)&nsb[(size_t)id.z*CC + c];
            float4 a3 = *(const float4*)&nsb[(size_t)id.w*CC + c];
            float4 o;
            o.x = w0*a0.x + w1*a1.x + w2*a2.x + w3*a3.x;
            o.y = w0*a0.y + w1*a1.y + w2*a2.y + w3*a3.y;
            o.z = w0*a0.z + w1*a1.z + w2*a2.z + w3*a3.z;
            o.w = w0*a0.w + w1*a1.w + w2*a2.w + w3*a3.w;
            *(float4*)&S->q[r][c] = o;
        }
    }

    const int xg  = tid >> 5;                 // logits rows: xg + 8p (warp-local rows)
    const int ygl = tid & 31;                 // logits cols: ygl + 32e
    const int xq  = tid >> 4;                 // PV rows: xq, xq+16
    const int cgq = tid & 15;                 // PV channels: 4cgq..+3 and 64+4cgq..+3

    float mrun[4], lrun[4];
    #pragma unroll
    for (int p = 0; p < 4; p++) { mrun[p] = -3.0e38f; lrun[p] = 0.f; }

    u64 oacc[2][4];                            // 2 rows x 8 ch (4 u64)
    #pragma unroll
    for (int r = 0; r < 2; r++)
        #pragma unroll
        for (int j = 0; j < 4; j++) oacc[r][j] = 0ull;

    for (int yt = 0; yt < 4; yt++) {
        const int y0 = yt << 6;
        const int ylo = max(y0 - 2, 0);
        __syncthreads();   // protect smem from previous iteration's readers

        // ---- stage ns, v (64x128 each), G window (36x68), radj (32x64) ----
        {
            const size_t base = ((size_t)b*TT + y0) << 7;
            for (int i = tid; i < 64*32; i += 256) {
                int r = i >> 5, c4 = i & 31;
                *(float4*)&S->ns[r][c4*4] = *(const float4*)(d_ns_buf + base + ((size_t)r << 7) + c4*4);
                *(float4*)&S->v [r][c4*4] = *(const float4*)(d_v_buf  + base + ((size_t)r << 7) + c4*4);
            }
            const float* Gp = d_G_buf + (size_t)b*TT*TT;
            for (int i = tid; i < 36*68; i += 256) {
                int r = i / 68, cc2 = i - r*68;
                int row = min(plo + r, TT-1);
                int col = min(ylo + cc2, TT-1);
                S->G[r][cc2] = Gp[row*TT + col];
            }
            for (int i = tid; i < 32*16; i += 256) {   // 512 int4
                int r = i >> 4, c4 = i & 15;
                ((int4*)S->rs[r])[c4] = *(const int4*)&radj[((size_t)b*TT + x0 + r)*TT + y0 + c4*4];
            }
        }
        __syncthreads();

        // ---- logits GEMM: 4 rows x 2 cols per thread ----
        u64 lacc[4][2];
        #pragma unroll
        for (int p = 0; p < 4; p++) { lacc[p][0] = 0ull; lacc[p][1] = 0ull; }

        for (int k4 = 0; k4 < 32; k4++) {
            F4U a[4], bb[2];
            #pragma unroll
            for (int p = 0; p < 4; p++) a[p].f4  = *(const float4*)&S->q [xg + 8*p ][4*k4];
            #pragma unroll
            for (int e = 0; e < 2; e++) bb[e].f4 = *(const float4*)&S->ns[ygl + 32*e][4*k4];
            #pragma unroll
            for (int p = 0; p < 4; p++)
                #pragma unroll
                for (int e = 0; e < 2; e++) {
                    ffma2(lacc[p][e], a[p].p[0], bb[e].p[0]);
                    ffma2(lacc[p][e], a[p].p[1], bb[e].p[1]);
                }
        }

        // ---- epilogue: + window-max + mask ----
        float wpfr[NEIGH];
        #pragma unroll
        for (int i = 0; i < NEIGH; i++) wpfr[i] = S->wpf[i];

        float sv[4][2];
        #pragma unroll
        for (int p = 0; p < 4; p++) {
            const int xl  = xg + 8*p;
            const int xgl = x0 + xl;
            const int startx = min(max(xgl - 2, 0), TT - NEIGH);
            const int sxr = startx - plo;
            #pragma unroll
            for (int e = 0; e < 2; e++) {
                const int yl  = ygl + 32*e;
                const int ygg = y0 + yl;
                const int starty = min(max(ygg - 2, 0), TT - NEIGH);
                const int syr = starty - ylo;
                float lo, hi; unpack2(lacc[p][e], lo, hi);
                float s = lo + hi;
                float spf = 0.f;
                #pragma unroll
                for (int i = 0; i < NEIGH; i++) {
                    const float* gr = S->G[sxr + i];
                    float mx = gr[syr];
                    #pragma unroll
                    for (int j = 1; j < NEIGH; j++) mx = fmaxf(mx, gr[syr + j]);
                    spf += wpfr[i] * mx;
                }
                float msk = (S->rs[xl][yl] == 0) ? -1e22f : 0.f;
                sv[p][e] = s + spf + msk;
            }
        }

        // ---- online softmax per row (row fully inside this warp) ----
        #pragma unroll
        for (int p = 0; p < 4; p++) {
            const int xl = xg + 8*p;
            float lm = fmaxf(sv[p][0], sv[p][1]);
            #pragma unroll
            for (int o = 16; o > 0; o >>= 1) lm = fmaxf(lm, __shfl_xor_sync(0xffffffffu, lm, o));
            float mnew = fmaxf(mrun[p], lm);
            float scale = __expf(mrun[p] - mnew);
            float p0 = __expf(sv[p][0] - mnew);
            float p1 = __expf(sv[p][1] - mnew);
            S->P[ygl     ][xl] = p0;
            S->P[ygl + 32][xl] = p1;
            float rs = p0 + p1;
            #pragma unroll
            for (int o = 16; o > 0; o >>= 1) rs += __shfl_xor_sync(0xffffffffu, rs, o);
            lrun[p] = lrun[p] * scale + rs;
            mrun[p] = mnew;
            if ((tid & 31) == 0) S->scl[xl] = scale;
        }
        __syncthreads();

        // ---- PV: rescale accs then accumulate this tile ----
        {
            u64 s0 = pack2(S->scl[xq], S->scl[xq]);
            u64 s1 = pack2(S->scl[xq + 16], S->scl[xq + 16]);
            #pragma unroll
            for (int j = 0; j < 4; j++) { fmul2(oacc[0][j], s0); fmul2(oacc[1][j], s1); }
        }
        #pragma unroll 4
        for (int y = 0; y < 64; y++) {
            float pa = S->P[y][xq];
            float pb = S->P[y][xq + 16];
            u64 pa2 = pack2(pa, pa);
            u64 pb2 = pack2(pb, pb);
            F4U v0, v1;
            v0.f4 = *(const float4*)&S->v[y][4*cgq];
            v1.f4 = *(const float4*)&S->v[y][64 + 4*cgq];
            ffma2(oacc[0][0], pa2, v0.p[0]);
            ffma2(oacc[0][1], pa2, v0.p[1]);
            ffma2(oacc[0][2], pa2, v1.p[0]);
            ffma2(oacc[0][3], pa2, v1.p[1]);
            ffma2(oacc[1][0], pb2, v0.p[0]);
            ffma2(oacc[1][1], pb2, v0.p[1]);
            ffma2(oacc[1][2], pb2, v1.p[0]);
            ffma2(oacc[1][3], pb2, v1.p[1]);
        }
    }

    // ---- finalize ----
    if ((tid & 31) == 0) {
        #pragma unroll
        for (int p = 0; p < 4; p++) S->lsh[xg + 8*p] = lrun[p];
    }
    __syncthreads();

    #pragma unroll
    for (int r = 0; r < 2; r++) {
        const int xl = xq + 16*r;
        const float inv = 1.f / S->lsh[xl];
        const size_t row = ((size_t)b*TT + x0 + xl) * CC;
        F4U o0, o1;
        unpack2(oacc[r][0], o0.f[0], o0.f[1]);
        unpack2(oacc[r][1], o0.f[2], o0.f[3]);
        unpack2(oacc[r][2], o1.f[0], o1.f[1]);
        unpack2(oacc[r][3], o1.f[2], o1.f[3]);
        #pragma unroll
        for (int j = 0; j < 4; j++) { o0.f[j] *= inv; o1.f[j] *= inv; }
        *(float4*)&out[row + 4*cgq]      = o0.f4;
        *(float4*)&out[row + 64 + 4*cgq] = o1.f4;
    }
}

// ---------------- launch ----------------
extern "C" void kernel_launch(void* const* d_in, const int* in_sizes, int n_in,
                              void* d_out, int out_size)
{
    const float* x    = (const float*)d_in[0];
    const int*   radj = (const int*)  d_in[1];
    const int*   inxs = (const int*)  d_in[2];
    const float* Wpf  = (const float*)d_in[3];
    const float* Wns  = (const float*)d_in[4];
    const float* Wv   = (const float*)d_in[5];
    const float* vpf  = (const float*)d_in[6];
    const float* gpf  = (const float*)d_in[7];
    const float* vns  = (const float*)d_in[8];
    const float* gns  = (const float*)d_in[9];
    float* out = (float*)d_out;

    const int gram_smem = (int)sizeof(GramSmem);
    const int attn_smem = (int)sizeof(AttnSmem);
    cudaFuncSetAttribute(gram_kernel, cudaFuncAttributeMaxDynamicSharedMemorySize, gram_smem);
    cudaFuncSetAttribute(attn_kernel, cudaFuncAttributeMaxDynamicSharedMemorySize, attn_smem);

    proj_kernel<<<dim3((BB*TT)/32, 3), 256>>>(x, Wpf, Wns, Wv);
    gram_kernel<<<BB*16, 256, gram_smem>>>();
    attn_kernel<<<BB*8, 256, attn_smem>>>(radj, inxs, vpf, gpf, vns, gns, out);
}

// round 11
// speedup vs baseline: 2.8717x; 1.0589x over previous
#include <cuda_runtime.h>
#include <math.h>

#define BB 32
#define TT 256
#define CC 128
#define TOPK 4
#define NEIGH 5

typedef unsigned long long u64;

union F4U { float4 f4; u64 p[2]; float f[4]; };

__device__ __forceinline__ void ffma2(u64& d, u64 a, u64 b) {
    asm("fma.rn.f32x2 %0, %1, %2, %0;" : "+l"(d) : "l"(a), "l"(b));
}
__device__ __forceinline__ void fmul2(u64& d, u64 a) {
    asm("mul.rn.f32x2 %0, %0, %1;" : "+l"(d) : "l"(a));
}
__device__ __forceinline__ u64 pack2(float lo, float hi) {
    u64 r;
    asm("mov.b64 %0, {%1, %2};" : "=l"(r) : "r"(__float_as_uint(lo)), "r"(__float_as_uint(hi)));
    return r;
}
__device__ __forceinline__ void unpack2(u64 v, float& lo, float& hi) {
    unsigned a, b;
    asm("mov.b64 {%0, %1}, %2;" : "=r"(a), "=r"(b) : "l"(v));
    lo = __uint_as_float(a); hi = __uint_as_float(b);
}

// ---------------- scratch ----------------
__device__ float d_pf_buf[BB*TT*CC];
__device__ float d_ns_buf[BB*TT*CC];
__device__ float d_v_buf [BB*TT*CC];
__device__ float d_G_buf [BB*TT*TT];

// ---------------- K1: projections + row-normalize (fma-bound GEMM) ----------------
// grid ((B*T)/64, 3), block 256. Warp w owns rows 8w..8w+7 (x broadcast from smem);
// lane l owns cols l+32j. 64 FFMA2 per 4 W-LDS.128 per k4 -> fma-pipe bound.
struct ProjSmem { float xsh[64][132]; float Wsh[128][36]; };

__global__ __launch_bounds__(256) void proj_kernel(const float* __restrict__ x,
                            const float* __restrict__ Wpf,
                            const float* __restrict__ Wns,
                            const float* __restrict__ Wv)
{
    extern __shared__ char smr[];
    ProjSmem* S = (ProjSmem*)smr;

    const int which = blockIdx.y;
    const float* __restrict__ W = (which == 0) ? Wpf : (which == 1) ? Wns : Wv;

    const int t0  = blockIdx.x * 64;
    const int tid = threadIdx.x;
    const int rw  = tid >> 5;     // warp id -> rows rw*8..rw*8+7
    const int l   = tid & 31;     // lane   -> cols l + 32j

    for (int i = tid; i < 64*32; i += 256) {
        int r = i >> 5, c4 = i & 31;
        *(float4*)&S->xsh[r][c4*4] = *(const float4*)&x[(t0 + r)*CC + c4*4];
    }

    u64 acc[8][4];
    #pragma unroll
    for (int i = 0; i < 8; i++)
        #pragma unroll
        for (int j = 0; j < 4; j++) acc[i][j] = 0ull;

    for (int k0 = 0; k0 < CC; k0 += 32) {
        __syncthreads();
        for (int i = tid; i < 128*8; i += 256) {
            int r = i >> 3, k4 = i & 7;
            *(float4*)&S->Wsh[r][k4*4] = *(const float4*)&W[r*CC + k0 + k4*4];
        }
        __syncthreads();

        #pragma unroll
        for (int k4 = 0; k4 < 8; k4++) {
            F4U bb[4];
            #pragma unroll
            for (int j = 0; j < 4; j++) bb[j].f4 = *(const float4*)&S->Wsh[l + 32*j][4*k4];
            #pragma unroll
            for (int i = 0; i < 8; i++) {
                F4U a; a.f4 = *(const float4*)&S->xsh[rw*8 + i][k0 + 4*k4];
                #pragma unroll
                for (int j = 0; j < 4; j++) {
                    ffma2(acc[i][j], a.p[0], bb[j].p[0]);
                    ffma2(acc[i][j], a.p[1], bb[j].p[1]);
                }
            }
        }
    }

    float* outp = (which == 0) ? d_pf_buf : (which == 1) ? d_ns_buf : d_v_buf;

    #pragma unroll
    for (int i = 0; i < 8; i++) {
        float o[4];
        #pragma unroll
        for (int j = 0; j < 4; j++) {
            float lo, hi; unpack2(acc[i][j], lo, hi);
            o[j] = lo + hi;
        }
        if (which != 2) {
            float s = o[0]*o[0] + o[1]*o[1] + o[2]*o[2] + o[3]*o[3];
            #pragma unroll
            for (int off = 16; off > 0; off >>= 1) s += __shfl_xor_sync(0xffffffffu, s, off);
            float inv = 1.f / fmaxf(sqrtf(s), 1e-12f);
            #pragma unroll
            for (int j = 0; j < 4; j++) o[j] *= inv;
        }
        const size_t row = (size_t)(t0 + rw*8 + i) * CC;
        #pragma unroll
        for (int j = 0; j < 4; j++)
            outp[row + l + 32*j] = o[j];
    }
}

// ---------------- K2: per-batch Gram  G = pf @ pf^T  (FFMA2, LDS.128) ----------------
struct GramSmem { float A[64][132]; float Bv[64][132]; };

__global__ __launch_bounds__(256) void gram_kernel()
{
    extern __shared__ char smr[];
    GramSmem* S = (GramSmem*)smr;

    const int b    = blockIdx.x >> 4;
    const int tile = blockIdx.x & 15;
    const int x0 = (tile >> 2) << 6;
    const int y0 = (tile & 3)  << 6;
    const float* base = d_pf_buf + (size_t)b*TT*CC;
    const int tid = threadIdx.x;

    for (int i = tid; i < 64*32; i += 256) {
        int r = i >> 5, c4 = i & 31;
        *(float4*)&S->A [r][c4*4] = *(const float4*)&base[(x0 + r)*CC + c4*4];
        *(float4*)&S->Bv[r][c4*4] = *(const float4*)&base[(y0 + r)*CC + c4*4];
    }
    __syncthreads();

    const int xg = tid >> 4;   // 16 groups, x = xg + 16p
    const int yg = tid & 15;   // 16 groups, y = yg + 16e

    u64 acc[4][4];
    #pragma unroll
    for (int p = 0; p < 4; p++)
        #pragma unroll
        for (int e = 0; e < 4; e++) acc[p][e] = 0ull;

    for (int k4 = 0; k4 < 32; k4++) {          // 4 k per iter
        F4U a[4], bb[4];
        #pragma unroll
        for (int p = 0; p < 4; p++) a[p].f4  = *(const float4*)&S->A [xg + 16*p][4*k4];
        #pragma unroll
        for (int e = 0; e < 4; e++) bb[e].f4 = *(const float4*)&S->Bv[yg + 16*e][4*k4];
        #pragma unroll
        for (int p = 0; p < 4; p++)
            #pragma unroll
            for (int e = 0; e < 4; e++) {
                ffma2(acc[p][e], a[p].p[0], bb[e].p[0]);
                ffma2(acc[p][e], a[p].p[1], bb[e].p[1]);
            }
    }

    float* Gp = d_G_buf + (size_t)b*TT*TT;
    #pragma unroll
    for (int p = 0; p < 4; p++)
        #pragma unroll
        for (int e = 0; e < 4; e++) {
            float lo, hi; unpack2(acc[p][e], lo, hi);
            Gp[(x0 + xg + 16*p)*TT + y0 + yg + 16*e] = lo + hi;
        }
}

// ---------------- K3: fused flash attention (qgather + logits + softmax + PV) ----------------
// grid B*8 = 256 blocks (32 x-rows each), block 256, ~111KB dynamic smem.
struct AttnSmem {
    float q [32][132];
    float ns[64][132];
    float v [64][132];
    float G [36][68];
    int   rs[32][64];
    float P [64][33];
    float scl[32];
    float lsh[32];
    float wpf[8];
    float wns[8];
};

__global__ __launch_bounds__(256) void attn_kernel(const int*  __restrict__ radj,
                            const int*  __restrict__ inxs,
                            const float* __restrict__ vpf,
                            const float* __restrict__ gpfv,
                            const float* __restrict__ vns,
                            const float* __restrict__ gnsv,
                            float* __restrict__ out)
{
    extern __shared__ char smr[];
    AttnSmem* S = (AttnSmem*)smr;

    const int b  = blockIdx.x >> 3;
    const int x0 = (blockIdx.x & 7) << 5;
    const int tid = threadIdx.x;
    const int plo = max(x0 - 2, 0);

    if (tid == 0) {
        float n = 0.f;
        for (int i = 0; i < NEIGH; i++) n += vpf[i]*vpf[i];
        float sc = gpfv[0] / sqrtf(n);
        for (int i = 0; i < NEIGH; i++) S->wpf[i] = vpf[i] * sc;
    }
    if (tid == 32) {
        float n = 0.f;
        for (int i = 0; i < TOPK; i++) n += vns[i]*vns[i];
        float sc = gnsv[0] / sqrtf(n);
        for (int i = 0; i < TOPK; i++) S->wns[i] = vns[i] * sc;
    }
    __syncthreads();

    // ---- q gather: row r = tid>>3, 16 channels per thread ----
    {
        const int r  = tid >> 3;
        const int cb = (tid & 7) * 16;
        int4 id = ((const int4*)inxs)[b*TT + x0 + r];
        float w0 = S->wns[0], w1 = S->wns[1], w2 = S->wns[2], w3 = S->wns[3];
        const float* nsb = d_ns_buf + (size_t)b*TT*CC;
        #pragma unroll
        for (int j = 0; j < 4; j++) {
            const int c = cb + 4*j;
            float4 a0 = *(const float4*)&nsb[(size_t)id.x*CC + c];
            float4 a1 = *(const float4*)&nsb[(size_t)id.y*CC + c];
            float4 a2 = *(const float4*)&nsb[(size_t)id.z*CC + c];
            float4 a3 = *(const float4*)&nsb[(size_t)id.w*CC + c];
            float4 o;
            o.x = w0*a0.x + w1*a1.x + w2*a2.x + w3*a3.x;
            o.y = w0*a0.y + w1*a1.y + w2*a2.y + w3*a3.y;
            o.z = w0*a0.z + w1*a1.z + w2*a2.z + w3*a3.z;
            o.w = w0*a0.w + w1*a1.w + w2*a2.w + w3*a3.w;
            *(float4*)&S->q[r][c] = o;
        }
    }

    const int xg  = tid >> 5;                 // logits rows: xg + 8p (warp-local rows)
    const int ygl = tid & 31;                 // logits cols: ygl + 32e
    const int rw4 = (tid >> 5) * 4;           // PV rows: rw4..rw4+3 (warp-owned -> P broadcast)
    const int lpv = tid & 31;                 // PV channels: 4*lpv..4*lpv+3

    float mrun[4], lrun[4];
    #pragma unroll
    for (int p = 0; p < 4; p++) { mrun[p] = -3.0e38f; lrun[p] = 0.f; }

    u64 oacc[4][2];                            // 4 rows x 4 ch (2 u64)
    #pragma unroll
    for (int r = 0; r < 4; r++) { oacc[r][0] = 0ull; oacc[r][1] = 0ull; }

    for (int yt = 0; yt < 4; yt++) {
        const int y0 = yt << 6;
        const int ylo = max(y0 - 2, 0);
        __syncthreads();   // protect smem from previous iteration's readers

        // ---- stage ns, v (64x128 each), G window (36x68), radj (32x64) ----
        {
            const size_t base = ((size_t)b*TT + y0) << 7;
            for (int i = tid; i < 64*32; i += 256) {
                int r = i >> 5, c4 = i & 31;
                *(float4*)&S->ns[r][c4*4] = *(const float4*)(d_ns_buf + base + ((size_t)r << 7) + c4*4);
                *(float4*)&S->v [r][c4*4] = *(const float4*)(d_v_buf  + base + ((size_t)r << 7) + c4*4);
            }
            const float* Gp = d_G_buf + (size_t)b*TT*TT;
            for (int i = tid; i < 36*68; i += 256) {
                int r = i / 68, cc2 = i - r*68;
                int row = min(plo + r, TT-1);
                int col = min(ylo + cc2, TT-1);
                S->G[r][cc2] = Gp[row*TT + col];
            }
            for (int i = tid; i < 32*16; i += 256) {   // 512 int4
                int r = i >> 4, c4 = i & 15;
                ((int4*)S->rs[r])[c4] = *(const int4*)&radj[((size_t)b*TT + x0 + r)*TT + y0 + c4*4];
            }
        }
        __syncthreads();

        // ---- logits GEMM: 4 rows x 2 cols per thread ----
        u64 lacc[4][2];
        #pragma unroll
        for (int p = 0; p < 4; p++) { lacc[p][0] = 0ull; lacc[p][1] = 0ull; }

        for (int k4 = 0; k4 < 32; k4++) {
            F4U a[4], bb[2];
            #pragma unroll
            for (int p = 0; p < 4; p++) a[p].f4  = *(const float4*)&S->q [xg + 8*p ][4*k4];
            #pragma unroll
            for (int e = 0; e < 2; e++) bb[e].f4 = *(const float4*)&S->ns[ygl + 32*e][4*k4];
            #pragma unroll
            for (int p = 0; p < 4; p++)
                #pragma unroll
                for (int e = 0; e < 2; e++) {
                    ffma2(lacc[p][e], a[p].p[0], bb[e].p[0]);
                    ffma2(lacc[p][e], a[p].p[1], bb[e].p[1]);
                }
        }

        // ---- epilogue: + window-max + mask ----
        float wpfr[NEIGH];
        #pragma unroll
        for (int i = 0; i < NEIGH; i++) wpfr[i] = S->wpf[i];

        float sv[4][2];
        #pragma unroll
        for (int p = 0; p < 4; p++) {
            const int xl  = xg + 8*p;
            const int xgl = x0 + xl;
            const int startx = min(max(xgl - 2, 0), TT - NEIGH);
            const int sxr = startx - plo;
            #pragma unroll
            for (int e = 0; e < 2; e++) {
                const int yl  = ygl + 32*e;
                const int ygg = y0 + yl;
                const int starty = min(max(ygg - 2, 0), TT - NEIGH);
                const int syr = starty - ylo;
                float lo, hi; unpack2(lacc[p][e], lo, hi);
                float s = lo + hi;
                float spf = 0.f;
                #pragma unroll
                for (int i = 0; i < NEIGH; i++) {
                    const float* gr = S->G[sxr + i];
                    float mx = gr[syr];
                    #pragma unroll
                    for (int j = 1; j < NEIGH; j++) mx = fmaxf(mx, gr[syr + j]);
                    spf += wpfr[i] * mx;
                }
                float msk = (S->rs[xl][yl] == 0) ? -1e22f : 0.f;
                sv[p][e] = s + spf + msk;
            }
        }

        // ---- online softmax per row (row fully inside this warp) ----
        #pragma unroll
        for (int p = 0; p < 4; p++) {
            const int xl = xg + 8*p;
            float lm = fmaxf(sv[p][0], sv[p][1]);
            #pragma unroll
            for (int o = 16; o > 0; o >>= 1) lm = fmaxf(lm, __shfl_xor_sync(0xffffffffu, lm, o));
            float mnew = fmaxf(mrun[p], lm);
            float scale = __expf(mrun[p] - mnew);
            float p0 = __expf(sv[p][0] - mnew);
            float p1 = __expf(sv[p][1] - mnew);
            S->P[ygl     ][xl] = p0;
            S->P[ygl + 32][xl] = p1;
            float rs = p0 + p1;
            #pragma unroll
            for (int o = 16; o > 0; o >>= 1) rs += __shfl_xor_sync(0xffffffffu, rs, o);
            lrun[p] = lrun[p] * scale + rs;
            mrun[p] = mnew;
            if ((tid & 31) == 0) S->scl[xl] = scale;
        }
        __syncthreads();

        // ---- PV: rescale accs then accumulate this tile ----
        // thread = 4 warp-owned rows (P broadcast) x 4 consecutive channels (1 LDS.128)
        #pragma unroll
        for (int r = 0; r < 4; r++) {
            float sc = S->scl[rw4 + r];
            u64 s2 = pack2(sc, sc);
            fmul2(oacc[r][0], s2); fmul2(oacc[r][1], s2);
        }
        #pragma unroll 4
        for (int y = 0; y < 64; y++) {
            F4U vv; vv.f4 = *(const float4*)&S->v[y][4*lpv];
            #pragma unroll
            for (int r = 0; r < 4; r++) {
                float p = S->P[y][rw4 + r];
                u64 p2 = pack2(p, p);
                ffma2(oacc[r][0], p2, vv.p[0]);
                ffma2(oacc[r][1], p2, vv.p[1]);
            }
        }
    }

    // ---- finalize ----
    if ((tid & 31) == 0) {
        #pragma unroll
        for (int p = 0; p < 4; p++) S->lsh[xg + 8*p] = lrun[p];
    }
    __syncthreads();

    #pragma unroll
    for (int r = 0; r < 4; r++) {
        const int xl = rw4 + r;
        const float inv = 1.f / S->lsh[xl];
        const size_t row = ((size_t)b*TT + x0 + xl) * CC;
        F4U o;
        unpack2(oacc[r][0], o.f[0], o.f[1]);
        unpack2(oacc[r][1], o.f[2], o.f[3]);
        #pragma unroll
        for (int j = 0; j < 4; j++) o.f[j] *= inv;
        *(float4*)&out[row + 4*lpv] = o.f4;
    }
}

// ---------------- launch ----------------
extern "C" void kernel_launch(void* const* d_in, const int* in_sizes, int n_in,
                              void* d_out, int out_size)
{
    const float* x    = (const float*)d_in[0];
    const int*   radj = (const int*)  d_in[1];
    const int*   inxs = (const int*)  d_in[2];
    const float* Wpf  = (const float*)d_in[3];
    const float* Wns  = (const float*)d_in[4];
    const float* Wv   = (const float*)d_in[5];
    const float* vpf  = (const float*)d_in[6];
    const float* gpf  = (const float*)d_in[7];
    const float* vns  = (const float*)d_in[8];
    const float* gns  = (const float*)d_in[9];
    float* out = (float*)d_out;

    const int proj_smem = (int)sizeof(ProjSmem);
    const int gram_smem = (int)sizeof(GramSmem);
    const int attn_smem = (int)sizeof(AttnSmem);
    cudaFuncSetAttribute(proj_kernel, cudaFuncAttributeMaxDynamicSharedMemorySize, proj_smem);
    cudaFuncSetAttribute(gram_kernel, cudaFuncAttributeMaxDynamicSharedMemorySize, gram_smem);
    cudaFuncSetAttribute(attn_kernel, cudaFuncAttributeMaxDynamicSharedMemorySize, attn_smem);

    proj_kernel<<<dim3((BB*TT)/64, 3), 256, proj_smem>>>(x, Wpf, Wns, Wv);
    gram_kernel<<<BB*16, 256, gram_smem>>>();
    attn_kernel<<<BB*8, 256, attn_smem>>>(radj, inxs, vpf, gpf, vns, gns, out);
}